// round 12
// baseline (speedup 1.0000x reference)
#include <cuda_runtime.h>
#include <cuda_bf16.h>
#include <stdint.h>

#define HDIM 1024
#define SEQ  2048
#define BATCH 4
#define MTOT (BATCH * SEQ)

typedef __nv_bfloat16 bf16;

// ---------------------------------------------------------------------------
// Panel geometry
// A-role panels: 128 rows x 32 k, [h 8KB | l 8KB] = 16KB
// B-role panels: 256 rows x 32 k, [h 16KB | l 16KB] = 32KB
// Within each half: 16B chunk (r, cc) at (r&7)*16 + (cc + 4*(r>>3))*128
// ---------------------------------------------------------------------------
#define PANEL_A 16384
#define PANEL_B 32768

// Scratch (__device__ globals: allocation-free rule)
__device__ __align__(128) char g_xp [(size_t)64 * 32 * PANEL_A];            // x   A-role
__device__ __align__(128) char g_wqp[(size_t)4  * 32 * PANEL_B];            // Wq  B-role
__device__ __align__(128) char g_wkp[(size_t)4  * 32 * PANEL_B];
__device__ __align__(128) char g_wvp[(size_t)4  * 32 * PANEL_B];
__device__ __align__(128) char g_qp [(size_t)64 * 32 * PANEL_A];            // Q   A-role
__device__ __align__(128) char g_kp [(size_t)32 * 32 * PANEL_B];            // K   B-role
__device__ __align__(128) char g_vtp[(size_t)BATCH * 4 * 64 * PANEL_B];     // V^T B-role
__device__ float g_p[(size_t)BATCH * SEQ * SEQ];                            // logits fp32
__device__ __align__(128) char g_pp [(size_t)64 * 64 * PANEL_A];            // probs A-role

// ---------------------------------------------------------------------------
// Helpers
// ---------------------------------------------------------------------------
__device__ __forceinline__ uint32_t smem_u32(const void* p) {
    uint32_t a;
    asm("{ .reg .u64 t; cvta.to.shared.u64 t, %1; cvt.u32.u64 %0, t; }" : "=r"(a) : "l"(p));
    return a;
}

__device__ __forceinline__ void ldsm4(uint32_t* r, uint32_t addr) {
    asm volatile("ldmatrix.sync.aligned.m8n8.x4.shared.b16 {%0,%1,%2,%3}, [%4];"
                 : "=r"(r[0]), "=r"(r[1]), "=r"(r[2]), "=r"(r[3]) : "r"(addr));
}

__device__ __forceinline__ void mma16816(float* d, const uint32_t* a, uint32_t b0, uint32_t b1) {
    asm volatile("mma.sync.aligned.m16n8k16.row.col.f32.bf16.bf16.f32 "
                 "{%0,%1,%2,%3}, {%4,%5,%6,%7}, {%8,%9}, {%0,%1,%2,%3};"
                 : "+f"(d[0]), "+f"(d[1]), "+f"(d[2]), "+f"(d[3])
                 : "r"(a[0]), "r"(a[1]), "r"(a[2]), "r"(a[3]), "r"(b0), "r"(b1));
}

__device__ __forceinline__ void bulk_g2s(uint32_t dst, const void* src, uint32_t bytes, uint32_t mbar) {
    asm volatile("cp.async.bulk.shared::cluster.global.mbarrier::complete_tx::bytes "
                 "[%0], [%1], %2, [%3];"
                 :: "r"(dst), "l"(src), "r"(bytes), "r"(mbar) : "memory");
}

#define MBAR_INIT(addr, cnt) \
    asm volatile("mbarrier.init.shared.b64 [%0], %1;" :: "r"(addr), "r"(cnt) : "memory")
#define MBAR_EXPECT_TX(addr, tx) \
    asm volatile("mbarrier.arrive.expect_tx.shared::cta.b64 _, [%0], %1;" :: "r"(addr), "r"(tx) : "memory")
#define FENCE_ASYNC_SHARED() asm volatile("fence.proxy.async.shared::cta;" ::: "memory")

#define MBAR_WAIT_PARITY(addr, par) do {                                             \
    uint32_t _mbar = (uint32_t)(addr);                                               \
    uint32_t _par  = (uint32_t)(par);                                                \
    uint32_t _done;                                                                  \
    asm volatile("{\n\t.reg .pred p;\n\t"                                            \
        "mbarrier.try_wait.parity.acquire.cta.shared::cta.b64 p, [%1], %2;\n\t"      \
        "selp.b32 %0, 1, 0, p;\n\t}"                                                 \
        : "=r"(_done) : "r"(_mbar), "r"(_par) : "memory");                           \
    if (!_done) {                                                                    \
        asm volatile("{\n\t.reg .pred P1;\n\t"                                       \
            "WAIT_LOOP_%=:\n\t"                                                      \
            "mbarrier.try_wait.parity.acquire.cta.shared::cta.b64 P1, [%0], %1, 0x989680;\n\t" \
            "@P1 bra.uni WAIT_DONE_%=;\n\t"                                          \
            "bra.uni WAIT_LOOP_%=;\n\t"                                              \
            "WAIT_DONE_%=:\n\t}"                                                     \
            :: "r"(_mbar), "r"(_par) : "memory");                                    \
    }                                                                                \
} while (0)

__device__ __forceinline__ void split1(float v, bf16& h, bf16& l) {
    h = __float2bfloat16_rn(v);
    l = __float2bfloat16_rn(v - __bfloat162float(h));
}

__device__ __host__ __forceinline__ uint32_t chunk_off(int r, int cc) {
    return (uint32_t)((r & 7) * 16 + (cc + 4 * (r >> 3)) * 128);
}

// ---------------------------------------------------------------------------
// GEMM: C[m0+i, n0+j] = sum_k A[m0+i,k]*B[n0+j,k], pre-packed panel operands.
// CTA 128x256, 16 warps (4m x 4n) of 32x64, BK=32, 4-stage bulk-copy ring.
// Stage layout: [Ah 8K][Al 8K][Bh 16K][Bl 16K] = 48KB.
// FROZEN as of R11 (measured at ~97% of legacy-HMMA rate ceiling).
// ---------------------------------------------------------------------------
#define STAGE_BYTES 49152
#define NSTAGE 4
#define SMEM_BYTES (1024 + NSTAGE * STAGE_BYTES)   // 197632
#define NTHREADS 512

// MODE 0: A-role split panels +bias | 1: B-role split panels +bias
// MODE 2: fp32 row store            | 3: B-role transposed split panels +bias
template <int MODE>
__device__ __forceinline__ void gemm_core(
    const char* __restrict__ Ap, const char* __restrict__ Bp,
    int K, const float* __restrict__ bias,
    char* __restrict__ outp, float* __restrict__ outf,
    int ldc, int m0, int n0, int cm0)
{
    extern __shared__ char smem[];
    const uint32_t sb = smem_u32(smem);
    const int tid = threadIdx.x, lane = tid & 31, wid = tid >> 5;
    const int wm = wid & 3, wn = wid >> 2;   // 4 x 4 warps, warp tile 32 x 64

    float acc[2][8][4];
#pragma unroll
    for (int i = 0; i < 2; i++)
#pragma unroll
        for (int j = 0; j < 8; j++)
#pragma unroll
            for (int e = 0; e < 4; e++) acc[i][j][e] = 0.f;

    const int NC = K >> 5;
    const size_t a_base = (size_t)(m0 >> 7) * NC;
    const size_t b_base = (size_t)(n0 >> 8) * NC;

    if (tid == 0) {
#pragma unroll
        for (int s = 0; s < NSTAGE; s++) MBAR_INIT(sb + s * 8, 1);
    }
    __syncthreads();
    FENCE_ASYNC_SHARED();

    auto issue = [&](int s) {
        const uint32_t mb  = sb + (uint32_t)(s & 3) * 8;
        const uint32_t dst = sb + 1024 + (uint32_t)(s & 3) * STAGE_BYTES;
        MBAR_EXPECT_TX(mb, (uint32_t)STAGE_BYTES);
        bulk_g2s(dst,           Ap + (a_base + s) * PANEL_A, PANEL_A, mb);
        bulk_g2s(dst + PANEL_A, Bp + (b_base + s) * PANEL_B, PANEL_B, mb);
    };

    if (tid == 0) { issue(0); issue(1); issue(2); }

    const uint32_t lsel = (lane & 7) * 16 + (lane >> 4) * 128 + ((lane >> 3) & 1) * 512;

#pragma unroll 1
    for (int c = 0; c < NC; c++) {
        MBAR_WAIT_PARITY(sb + (c & 3) * 8, (c >> 2) & 1);
        __syncthreads();
        if (tid == 0 && c + 3 < NC) issue(c + 3);

        const uint32_t base = sb + 1024 + (uint32_t)(c & 3) * STAGE_BYTES;

#pragma unroll
        for (int ks = 0; ks < 2; ks++) {
            const uint32_t koff = (uint32_t)ks * 256;
            uint32_t ah[2][4], al[2][4];
#pragma unroll
            for (int mi = 0; mi < 2; mi++) {
                uint32_t g = (uint32_t)(wm * 4 + mi * 2);
                uint32_t off = base + lsel + koff + g * 512;
                ldsm4(ah[mi], off);
                ldsm4(al[mi], off + 8192);
            }
#pragma unroll
            for (int bi = 0; bi < 4; bi++) {
                uint32_t g = (uint32_t)(wn * 8 + bi * 2);
                uint32_t off = base + 16384 + lsel + koff + g * 512;
                uint32_t bh[4], bl[4];
                ldsm4(bh, off);
                ldsm4(bl, off + 16384);
#pragma unroll
                for (int mi = 0; mi < 2; mi++)
#pragma unroll
                    for (int j = 0; j < 2; j++) {
                        const int ni = bi * 2 + j;
                        mma16816(acc[mi][ni], ah[mi], bh[j], bh[j + 2]);
                        mma16816(acc[mi][ni], ah[mi], bl[j], bl[j + 2]);
                        mma16816(acc[mi][ni], al[mi], bh[j], bh[j + 2]);
                    }
            }
        }
    }

    // epilogue — C frag: rows (lane>>2)+{0,8}, cols 2*(lane&3)+{0,1}
    const int rl = lane >> 2, cl = (lane & 3) * 2;
#pragma unroll
    for (int mi = 0; mi < 2; mi++)
#pragma unroll
        for (int ni = 0; ni < 8; ni++) {
            const int col = n0 + wn * 64 + ni * 8 + cl;
#pragma unroll
            for (int rh = 0; rh < 2; rh++) {
                float v0 = acc[mi][ni][rh * 2 + 0];
                float v1 = acc[mi][ni][rh * 2 + 1];
                if (MODE != 2) {
                    v0 += __ldg(bias + col);
                    v1 += __ldg(bias + col + 1);
                }
                const int row = m0 + wm * 32 + mi * 16 + rl + rh * 8;
                if (MODE == 2) {
                    float2 o = {v0, v1};
                    *(float2*)(outf + (size_t)row * ldc + col) = o;
                } else if (MODE == 0) {   // A-role panels, k-width = ldc
                    bf16 h0, l0, h1, l1;
                    split1(v0, h0, l0); split1(v1, h1, l1);
                    uint32_t hp = ((uint32_t)__bfloat16_as_ushort(h1) << 16) | __bfloat16_as_ushort(h0);
                    uint32_t lp = ((uint32_t)__bfloat16_as_ushort(l1) << 16) | __bfloat16_as_ushort(l0);
                    size_t off = ((size_t)(row >> 7) * (ldc >> 5) + (col >> 5)) * PANEL_A
                               + chunk_off(row & 127, (col & 31) >> 3) + (col & 7) * 2;
                    *(uint32_t*)(outp + off)        = hp;
                    *(uint32_t*)(outp + off + 8192) = lp;
                } else if (MODE == 1) {   // B-role panels, k-width = ldc
                    bf16 h0, l0, h1, l1;
                    split1(v0, h0, l0); split1(v1, h1, l1);
                    uint32_t hp = ((uint32_t)__bfloat16_as_ushort(h1) << 16) | __bfloat16_as_ushort(h0);
                    uint32_t lp = ((uint32_t)__bfloat16_as_ushort(l1) << 16) | __bfloat16_as_ushort(l0);
                    size_t off = ((size_t)(row >> 8) * (ldc >> 5) + (col >> 5)) * PANEL_B
                               + chunk_off(row & 255, (col & 31) >> 3) + (col & 7) * 2;
                    *(uint32_t*)(outp + off)         = hp;
                    *(uint32_t*)(outp + off + 16384) = lp;
                } else {                  // MODE 3: V^T, B-role rows = col(h), k = local seq
                    const int mloc = cm0 + wm * 32 + mi * 16 + rl + rh * 8;
                    bf16 h0, l0, h1, l1;
                    split1(v0, h0, l0); split1(v1, h1, l1);
                    size_t pb = ((size_t)(col >> 8) * (SEQ >> 5) + (mloc >> 5)) * PANEL_B;
                    uint32_t co0 = chunk_off(col & 255, (mloc & 31) >> 3) + (mloc & 7) * 2;
                    uint32_t co1 = chunk_off((col + 1) & 255, (mloc & 31) >> 3) + (mloc & 7) * 2;
                    *(bf16*)(outp + pb + co0)         = h0;
                    *(bf16*)(outp + pb + co0 + 16384) = l0;
                    *(bf16*)(outp + pb + co1)         = h1;
                    *(bf16*)(outp + pb + co1 + 16384) = l1;
                }
            }
        }
}

// ---------------------------------------------------------------------------
// Fused split: one launch packs x (A-role) + Wq/Wk/Wv (B-role)
// ---------------------------------------------------------------------------
__global__ void __launch_bounds__(256) split_fused(
    const float* __restrict__ x, const float* __restrict__ Wq,
    const float* __restrict__ Wk, const float* __restrict__ Wv,
    char* __restrict__ xp, char* __restrict__ wqp,
    char* __restrict__ wkp, char* __restrict__ wvp)
{
    const int bid = blockIdx.x;
    const float* src;
    char* dst;
    int i;
    bool arole;
    if (bid < 8192) {            // x: 8192x1024 fp32, A-role
        src = x; dst = xp; i = bid * 256 + threadIdx.x; arole = true;
    } else {
        const int w = (bid - 8192) >> 10;
        const int b2 = (bid - 8192) & 1023;
        src = (w == 0) ? Wq : (w == 1) ? Wk : Wv;
        dst = (w == 0) ? wqp : (w == 1) ? wkp : wvp;
        i = b2 * 256 + threadIdx.x; arole = false;
    }
    const int idx = i * 4;
    const int row = idx >> 10, k = idx & 1023;
    float4 v = *(const float4*)(src + idx);
    float f[4] = {v.x, v.y, v.z, v.w};
    uint32_t hp[2], lp[2];
#pragma unroll
    for (int j = 0; j < 2; j++) {
        bf16 h0, l0, h1, l1;
        split1(f[2 * j], h0, l0); split1(f[2 * j + 1], h1, l1);
        hp[j] = ((uint32_t)__bfloat16_as_ushort(h1) << 16) | __bfloat16_as_ushort(h0);
        lp[j] = ((uint32_t)__bfloat16_as_ushort(l1) << 16) | __bfloat16_as_ushort(l0);
    }
    if (arole) {
        size_t off = ((size_t)(row >> 7) * 32 + (k >> 5)) * PANEL_A
                   + chunk_off(row & 127, (k & 31) >> 3) + (k & 7) * 2;
        *(uint2*)(dst + off)        = make_uint2(hp[0], hp[1]);
        *(uint2*)(dst + off + 8192) = make_uint2(lp[0], lp[1]);
    } else {
        size_t off = ((size_t)(row >> 8) * 32 + (k >> 5)) * PANEL_B
                   + chunk_off(row & 255, (k & 31) >> 3) + (k & 7) * 2;
        *(uint2*)(dst + off)         = make_uint2(hp[0], hp[1]);
        *(uint2*)(dst + off + 16384) = make_uint2(lp[0], lp[1]);
    }
}

// ---------------------------------------------------------------------------
// GEMM kernels
// ---------------------------------------------------------------------------
__global__ void __launch_bounds__(NTHREADS, 1) qkv_tc(
    const float* __restrict__ bq, const float* __restrict__ bk, const float* __restrict__ bv)
{
    const int m0 = blockIdx.y * 128;
    const int n0 = blockIdx.x * 256;
    if (blockIdx.z == 0) {
        gemm_core<0>(g_xp, g_wqp, HDIM, bq, g_qp, nullptr, HDIM, m0, n0, 0);
    } else if (blockIdx.z == 1) {
        gemm_core<1>(g_xp, g_wkp, HDIM, bk, g_kp, nullptr, HDIM, m0, n0, 0);
    } else {
        const int b = m0 >> 11;
        gemm_core<3>(g_xp, g_wvp, HDIM, bv,
                     g_vtp + (size_t)b * 4 * 64 * PANEL_B, nullptr, SEQ,
                     m0, n0, m0 & (SEQ - 1));
    }
}

__global__ void __launch_bounds__(NTHREADS, 1) scores_tc()
{
    const int b = blockIdx.z;
    gemm_core<2>(g_qp + (size_t)b * 16 * 32 * PANEL_A,
                 g_kp + (size_t)b * 8 * 32 * PANEL_B,
                 HDIM, nullptr, nullptr,
                 g_p + (size_t)b * SEQ * SEQ, SEQ,
                 blockIdx.y * 128, blockIdx.x * 256, 0);
}

__global__ void __launch_bounds__(NTHREADS, 1) context_tc(float* __restrict__ ctx)
{
    const int b = blockIdx.z;
    gemm_core<2>(g_pp + (size_t)b * 16 * 64 * PANEL_A,
                 g_vtp + (size_t)b * 4 * 64 * PANEL_B,
                 SEQ, nullptr, nullptr,
                 ctx + (size_t)b * SEQ * HDIM, HDIM,
                 blockIdx.y * 128, blockIdx.x * 256, 0);
}

// ---------------------------------------------------------------------------
// Softmax: fp32 logits -> split probs in A-role panels (vectorized IO)
// ---------------------------------------------------------------------------
__global__ void __launch_bounds__(256) softmax_kernel()
{
    const int row = blockIdx.x;
    const float4* p4 = (const float4*)(g_p + (size_t)row * SEQ) + threadIdx.x * 2;
    const int tid = threadIdx.x;

    float4 va = p4[0], vb = p4[1];
    float v[8] = {va.x, va.y, va.z, va.w, vb.x, vb.y, vb.z, vb.w};
    float m = v[0];
#pragma unroll
    for (int i = 1; i < 8; i++) m = fmaxf(m, v[i]);

    __shared__ float red[8];
#pragma unroll
    for (int o = 16; o; o >>= 1) m = fmaxf(m, __shfl_xor_sync(0xffffffffu, m, o));
    if ((tid & 31) == 0) red[tid >> 5] = m;
    __syncthreads();
    m = red[0];
#pragma unroll
    for (int i = 1; i < 8; i++) m = fmaxf(m, red[i]);
    __syncthreads();

    float s = 0.f;
#pragma unroll
    for (int i = 0; i < 8; i++) {
        v[i] = __expf(v[i] - m);
        s += v[i];
    }
#pragma unroll
    for (int o = 16; o; o >>= 1) s += __shfl_xor_sync(0xffffffffu, s, o);
    if ((tid & 31) == 0) red[tid >> 5] = s;
    __syncthreads();
    float tot = 0.f;
#pragma unroll
    for (int i = 0; i < 8; i++) tot += red[i];
    const float inv = 1.0f / tot;

    // 8 consecutive cols per thread -> one 16B h-store + one 16B l-store.
    // cols [tid*8, tid*8+8) lie in one k-chunk (cc = (col&31)>>3 constant,
    // (col&7)*2 spans the 16B chunk exactly).
    uint32_t hp[4], lp[4];
#pragma unroll
    for (int j = 0; j < 4; j++) {
        bf16 h0, l0, h1, l1;
        split1(v[2 * j] * inv, h0, l0);
        split1(v[2 * j + 1] * inv, h1, l1);
        hp[j] = ((uint32_t)__bfloat16_as_ushort(h1) << 16) | __bfloat16_as_ushort(h0);
        lp[j] = ((uint32_t)__bfloat16_as_ushort(l1) << 16) | __bfloat16_as_ushort(l0);
    }
    const int col0 = tid * 8;
    const size_t off = ((size_t)(row >> 7) * 64 + (col0 >> 5)) * PANEL_A
                     + chunk_off(row & 127, (col0 & 31) >> 3);
    *(uint4*)(g_pp + off)        = make_uint4(hp[0], hp[1], hp[2], hp[3]);
    *(uint4*)(g_pp + off + 8192) = make_uint4(lp[0], lp[1], lp[2], lp[3]);
}

// ---------------------------------------------------------------------------
// Column sums of probs, per-panel reduction
// ---------------------------------------------------------------------------
__global__ void __launch_bounds__(256) colsum_kernel(float* __restrict__ out)
{
    const int pk = blockIdx.x;   // 0..63 k-panel
    const int pr = blockIdx.y;   // 0..63 row-panel
    const char* panel = g_pp + ((size_t)pr * 64 + pk) * PANEL_A;
    const int tid = threadIdx.x;
    const int col = tid & 31;
    const int rg  = tid >> 5;    // 8 groups of 16 rows

    const uint32_t cbase = ((col & 31) >> 3) * 128 + (col & 7) * 2;
    float s = 0.f;
#pragma unroll
    for (int r = rg * 16; r < rg * 16 + 16; r++) {
        uint32_t off = (uint32_t)((r & 7) * 16 + 4 * (r >> 3) * 128) + cbase;
        s += __bfloat162float(*(const bf16*)(panel + off))
           + __bfloat162float(*(const bf16*)(panel + off + 8192));
    }
    __shared__ float part[256];
    part[tid] = s;
    __syncthreads();
    if (tid < 32) {
        float t = 0.f;
#pragma unroll
        for (int j = 0; j < 8; j++) t += part[tid + 32 * j];
        const int batch = pr >> 4;
        atomicAdd(out + batch * SEQ + pk * 32 + tid, t);
    }
}

// ---------------------------------------------------------------------------
extern "C" void kernel_launch(void* const* d_in, const int* in_sizes, int n_in,
                              void* d_out, int out_size)
{
    const float* x  = (const float*)d_in[0];
    const float* Wq = (const float*)d_in[1];
    const float* bq = (const float*)d_in[2];
    const float* Wk = (const float*)d_in[3];
    const float* bk = (const float*)d_in[4];
    const float* Wv = (const float*)d_in[5];
    const float* bv = (const float*)d_in[6];

    float* ctx = (float*)d_out;
    float* sc  = ctx + (size_t)BATCH * SEQ * HDIM;

    cudaFuncSetAttribute((const void*)qkv_tc,
                         cudaFuncAttributeMaxDynamicSharedMemorySize, SMEM_BYTES);
    cudaFuncSetAttribute((const void*)scores_tc,
                         cudaFuncAttributeMaxDynamicSharedMemorySize, SMEM_BYTES);
    cudaFuncSetAttribute((const void*)context_tc,
                         cudaFuncAttributeMaxDynamicSharedMemorySize, SMEM_BYTES);

    char *xp, *wqp, *wkp, *wvp;
    cudaGetSymbolAddress((void**)&xp,  g_xp);
    cudaGetSymbolAddress((void**)&wqp, g_wqp);
    cudaGetSymbolAddress((void**)&wkp, g_wkp);
    cudaGetSymbolAddress((void**)&wvp, g_wvp);

    cudaMemsetAsync(sc, 0, (size_t)BATCH * SEQ * sizeof(float));

    split_fused<<<8192 + 3 * 1024, 256>>>(x, Wq, Wk, Wv, xp, wqp, wkp, wvp);

    qkv_tc<<<dim3(HDIM / 256, MTOT / 128, 3), NTHREADS, SMEM_BYTES>>>(bq, bk, bv);
    scores_tc<<<dim3(SEQ / 256, SEQ / 128, BATCH), NTHREADS, SMEM_BYTES>>>();
    softmax_kernel<<<MTOT, 256>>>();
    colsum_kernel<<<dim3(64, 64), 256>>>(sc);
    context_tc<<<dim3(HDIM / 256, SEQ / 128, BATCH), NTHREADS, SMEM_BYTES>>>(ctx);
}

// round 13
// speedup vs baseline: 1.0143x; 1.0143x over previous
#include <cuda_runtime.h>
#include <cuda_bf16.h>
#include <stdint.h>

#define HDIM 1024
#define SEQ  2048
#define BATCH 4
#define MTOT (BATCH * SEQ)

typedef __nv_bfloat16 bf16;

// ---------------------------------------------------------------------------
// Panel geometry
// A-role panels: 128 rows x 32 k, [h 8KB | l 8KB] = 16KB
// B-role panels: 256 rows x 32 k, [h 16KB | l 16KB] = 32KB
// Within each half: 16B chunk (r, cc) at (r&7)*16 + (cc + 4*(r>>3))*128
// ---------------------------------------------------------------------------
#define PANEL_A 16384
#define PANEL_B 32768

// Scratch (__device__ globals: allocation-free rule)
__device__ __align__(128) char g_xp [(size_t)64 * 32 * PANEL_A];            // x   A-role
__device__ __align__(128) char g_wqp[(size_t)4  * 32 * PANEL_B];            // Wq  B-role
__device__ __align__(128) char g_wkp[(size_t)4  * 32 * PANEL_B];
__device__ __align__(128) char g_wvp[(size_t)4  * 32 * PANEL_B];
__device__ __align__(128) char g_qp [(size_t)64 * 32 * PANEL_A];            // Q   A-role
__device__ __align__(128) char g_kp [(size_t)32 * 32 * PANEL_B];            // K   B-role
__device__ __align__(128) char g_vtp[(size_t)BATCH * 4 * 64 * PANEL_B];     // V^T B-role
__device__ float g_p [(size_t)BATCH * SEQ * SEQ];                           // logits partial 0
__device__ float g_p2[(size_t)BATCH * SEQ * SEQ];                           // logits partial 1
__device__ __align__(128) char g_pp [(size_t)64 * 64 * PANEL_A];            // probs A-role

// ---------------------------------------------------------------------------
// Helpers
// ---------------------------------------------------------------------------
__device__ __forceinline__ uint32_t smem_u32(const void* p) {
    uint32_t a;
    asm("{ .reg .u64 t; cvta.to.shared.u64 t, %1; cvt.u32.u64 %0, t; }" : "=r"(a) : "l"(p));
    return a;
}

__device__ __forceinline__ void ldsm4(uint32_t* r, uint32_t addr) {
    asm volatile("ldmatrix.sync.aligned.m8n8.x4.shared.b16 {%0,%1,%2,%3}, [%4];"
                 : "=r"(r[0]), "=r"(r[1]), "=r"(r[2]), "=r"(r[3]) : "r"(addr));
}

__device__ __forceinline__ void mma16816(float* d, const uint32_t* a, uint32_t b0, uint32_t b1) {
    asm volatile("mma.sync.aligned.m16n8k16.row.col.f32.bf16.bf16.f32 "
                 "{%0,%1,%2,%3}, {%4,%5,%6,%7}, {%8,%9}, {%0,%1,%2,%3};"
                 : "+f"(d[0]), "+f"(d[1]), "+f"(d[2]), "+f"(d[3])
                 : "r"(a[0]), "r"(a[1]), "r"(a[2]), "r"(a[3]), "r"(b0), "r"(b1));
}

__device__ __forceinline__ void bulk_g2s(uint32_t dst, const void* src, uint32_t bytes, uint32_t mbar) {
    asm volatile("cp.async.bulk.shared::cluster.global.mbarrier::complete_tx::bytes "
                 "[%0], [%1], %2, [%3];"
                 :: "r"(dst), "l"(src), "r"(bytes), "r"(mbar) : "memory");
}

#define MBAR_INIT(addr, cnt) \
    asm volatile("mbarrier.init.shared.b64 [%0], %1;" :: "r"(addr), "r"(cnt) : "memory")
#define MBAR_EXPECT_TX(addr, tx) \
    asm volatile("mbarrier.arrive.expect_tx.shared::cta.b64 _, [%0], %1;" :: "r"(addr), "r"(tx) : "memory")
#define FENCE_ASYNC_SHARED() asm volatile("fence.proxy.async.shared::cta;" ::: "memory")

#define MBAR_WAIT_PARITY(addr, par) do {                                             \
    uint32_t _mbar = (uint32_t)(addr);                                               \
    uint32_t _par  = (uint32_t)(par);                                                \
    uint32_t _done;                                                                  \
    asm volatile("{\n\t.reg .pred p;\n\t"                                            \
        "mbarrier.try_wait.parity.acquire.cta.shared::cta.b64 p, [%1], %2;\n\t"      \
        "selp.b32 %0, 1, 0, p;\n\t}"                                                 \
        : "=r"(_done) : "r"(_mbar), "r"(_par) : "memory");                           \
    if (!_done) {                                                                    \
        asm volatile("{\n\t.reg .pred P1;\n\t"                                       \
            "WAIT_LOOP_%=:\n\t"                                                      \
            "mbarrier.try_wait.parity.acquire.cta.shared::cta.b64 P1, [%0], %1, 0x989680;\n\t" \
            "@P1 bra.uni WAIT_DONE_%=;\n\t"                                          \
            "bra.uni WAIT_LOOP_%=;\n\t"                                              \
            "WAIT_DONE_%=:\n\t}"                                                     \
            :: "r"(_mbar), "r"(_par) : "memory");                                    \
    }                                                                                \
} while (0)

__device__ __forceinline__ void split1(float v, bf16& h, bf16& l) {
    h = __float2bfloat16_rn(v);
    l = __float2bfloat16_rn(v - __bfloat162float(h));
}

__device__ __host__ __forceinline__ uint32_t chunk_off(int r, int cc) {
    return (uint32_t)((r & 7) * 16 + (cc + 4 * (r >> 3)) * 128);
}

// ---------------------------------------------------------------------------
// GEMM: C[m0+i, n0+j] = sum_k A[m0+i,k]*B[n0+j,k], pre-packed panel operands.
// CTA 128x256, 16 warps (4m x 4n) of 32x64, BK=32, 4-stage bulk-copy ring.
// Stage layout: [Ah 8K][Al 8K][Bh 16K][Bl 16K] = 48KB.
// FROZEN inner loop (R11: ~97% of legacy-HMMA rate ceiling).
// NCT = panels per full tile row (compile-time), C0 = starting panel
// (compile-time). For qkv/context these instantiate to the exact constants
// the R12 build derived at runtime — codegen unchanged.
// ---------------------------------------------------------------------------
#define STAGE_BYTES 49152
#define NSTAGE 4
#define SMEM_BYTES (1024 + NSTAGE * STAGE_BYTES)   // 197632
#define NTHREADS 512

// MODE 0: A-role split panels +bias | 1: B-role split panels +bias
// MODE 2: fp32 row store            | 3: B-role transposed split panels +bias
template <int MODE, int NCT, int C0>
__device__ __forceinline__ void gemm_core(
    const char* __restrict__ Ap, const char* __restrict__ Bp,
    int K, const float* __restrict__ bias,
    char* __restrict__ outp, float* __restrict__ outf,
    int ldc, int m0, int n0, int cm0)
{
    extern __shared__ char smem[];
    const uint32_t sb = smem_u32(smem);
    const int tid = threadIdx.x, lane = tid & 31, wid = tid >> 5;
    const int wm = wid & 3, wn = wid >> 2;   // 4 x 4 warps, warp tile 32 x 64

    float acc[2][8][4];
#pragma unroll
    for (int i = 0; i < 2; i++)
#pragma unroll
        for (int j = 0; j < 8; j++)
#pragma unroll
            for (int e = 0; e < 4; e++) acc[i][j][e] = 0.f;

    const int NC = K >> 5;
    const size_t a_base = (size_t)(m0 >> 7) * NCT + C0;
    const size_t b_base = (size_t)(n0 >> 8) * NCT + C0;

    if (tid == 0) {
#pragma unroll
        for (int s = 0; s < NSTAGE; s++) MBAR_INIT(sb + s * 8, 1);
    }
    __syncthreads();
    FENCE_ASYNC_SHARED();

    auto issue = [&](int s) {
        const uint32_t mb  = sb + (uint32_t)(s & 3) * 8;
        const uint32_t dst = sb + 1024 + (uint32_t)(s & 3) * STAGE_BYTES;
        MBAR_EXPECT_TX(mb, (uint32_t)STAGE_BYTES);
        bulk_g2s(dst,           Ap + (a_base + s) * PANEL_A, PANEL_A, mb);
        bulk_g2s(dst + PANEL_A, Bp + (b_base + s) * PANEL_B, PANEL_B, mb);
    };

    if (tid == 0) { issue(0); issue(1); issue(2); }

    const uint32_t lsel = (lane & 7) * 16 + (lane >> 4) * 128 + ((lane >> 3) & 1) * 512;

#pragma unroll 1
    for (int c = 0; c < NC; c++) {
        MBAR_WAIT_PARITY(sb + (c & 3) * 8, (c >> 2) & 1);
        __syncthreads();
        if (tid == 0 && c + 3 < NC) issue(c + 3);

        const uint32_t base = sb + 1024 + (uint32_t)(c & 3) * STAGE_BYTES;

#pragma unroll
        for (int ks = 0; ks < 2; ks++) {
            const uint32_t koff = (uint32_t)ks * 256;
            uint32_t ah[2][4], al[2][4];
#pragma unroll
            for (int mi = 0; mi < 2; mi++) {
                uint32_t g = (uint32_t)(wm * 4 + mi * 2);
                uint32_t off = base + lsel + koff + g * 512;
                ldsm4(ah[mi], off);
                ldsm4(al[mi], off + 8192);
            }
#pragma unroll
            for (int bi = 0; bi < 4; bi++) {
                uint32_t g = (uint32_t)(wn * 8 + bi * 2);
                uint32_t off = base + 16384 + lsel + koff + g * 512;
                uint32_t bh[4], bl[4];
                ldsm4(bh, off);
                ldsm4(bl, off + 16384);
#pragma unroll
                for (int mi = 0; mi < 2; mi++)
#pragma unroll
                    for (int j = 0; j < 2; j++) {
                        const int ni = bi * 2 + j;
                        mma16816(acc[mi][ni], ah[mi], bh[j], bh[j + 2]);
                        mma16816(acc[mi][ni], ah[mi], bl[j], bl[j + 2]);
                        mma16816(acc[mi][ni], al[mi], bh[j], bh[j + 2]);
                    }
            }
        }
    }

    // epilogue — C frag: rows (lane>>2)+{0,8}, cols 2*(lane&3)+{0,1}
    const int rl = lane >> 2, cl = (lane & 3) * 2;
#pragma unroll
    for (int mi = 0; mi < 2; mi++)
#pragma unroll
        for (int ni = 0; ni < 8; ni++) {
            const int col = n0 + wn * 64 + ni * 8 + cl;
#pragma unroll
            for (int rh = 0; rh < 2; rh++) {
                float v0 = acc[mi][ni][rh * 2 + 0];
                float v1 = acc[mi][ni][rh * 2 + 1];
                if (MODE != 2) {
                    v0 += __ldg(bias + col);
                    v1 += __ldg(bias + col + 1);
                }
                const int row = m0 + wm * 32 + mi * 16 + rl + rh * 8;
                if (MODE == 2) {
                    float2 o = {v0, v1};
                    *(float2*)(outf + (size_t)row * ldc + col) = o;
                } else if (MODE == 0) {   // A-role panels, k-width = ldc
                    bf16 h0, l0, h1, l1;
                    split1(v0, h0, l0); split1(v1, h1, l1);
                    uint32_t hp = ((uint32_t)__bfloat16_as_ushort(h1) << 16) | __bfloat16_as_ushort(h0);
                    uint32_t lp = ((uint32_t)__bfloat16_as_ushort(l1) << 16) | __bfloat16_as_ushort(l0);
                    size_t off = ((size_t)(row >> 7) * (ldc >> 5) + (col >> 5)) * PANEL_A
                               + chunk_off(row & 127, (col & 31) >> 3) + (col & 7) * 2;
                    *(uint32_t*)(outp + off)        = hp;
                    *(uint32_t*)(outp + off + 8192) = lp;
                } else if (MODE == 1) {   // B-role panels, k-width = ldc
                    bf16 h0, l0, h1, l1;
                    split1(v0, h0, l0); split1(v1, h1, l1);
                    uint32_t hp = ((uint32_t)__bfloat16_as_ushort(h1) << 16) | __bfloat16_as_ushort(h0);
                    uint32_t lp = ((uint32_t)__bfloat16_as_ushort(l1) << 16) | __bfloat16_as_ushort(l0);
                    size_t off = ((size_t)(row >> 8) * (ldc >> 5) + (col >> 5)) * PANEL_B
                               + chunk_off(row & 255, (col & 31) >> 3) + (col & 7) * 2;
                    *(uint32_t*)(outp + off)         = hp;
                    *(uint32_t*)(outp + off + 16384) = lp;
                } else {                  // MODE 3: V^T, B-role rows = col(h), k = local seq
                    const int mloc = cm0 + wm * 32 + mi * 16 + rl + rh * 8;
                    bf16 h0, l0, h1, l1;
                    split1(v0, h0, l0); split1(v1, h1, l1);
                    size_t pb = ((size_t)(col >> 8) * (SEQ >> 5) + (mloc >> 5)) * PANEL_B;
                    uint32_t co0 = chunk_off(col & 255, (mloc & 31) >> 3) + (mloc & 7) * 2;
                    uint32_t co1 = chunk_off((col + 1) & 255, (mloc & 31) >> 3) + (mloc & 7) * 2;
                    *(bf16*)(outp + pb + co0)         = h0;
                    *(bf16*)(outp + pb + co0 + 16384) = l0;
                    *(bf16*)(outp + pb + co1)         = h1;
                    *(bf16*)(outp + pb + co1 + 16384) = l1;
                }
            }
        }
}

// ---------------------------------------------------------------------------
// Fused split: one launch packs x (A-role) + Wq/Wk/Wv (B-role)
// ---------------------------------------------------------------------------
__global__ void __launch_bounds__(256) split_fused(
    const float* __restrict__ x, const float* __restrict__ Wq,
    const float* __restrict__ Wk, const float* __restrict__ Wv,
    char* __restrict__ xp, char* __restrict__ wqp,
    char* __restrict__ wkp, char* __restrict__ wvp)
{
    const int bid = blockIdx.x;
    const float* src;
    char* dst;
    int i;
    bool arole;
    if (bid < 8192) {            // x: 8192x1024 fp32, A-role
        src = x; dst = xp; i = bid * 256 + threadIdx.x; arole = true;
    } else {
        const int w = (bid - 8192) >> 10;
        const int b2 = (bid - 8192) & 1023;
        src = (w == 0) ? Wq : (w == 1) ? Wk : Wv;
        dst = (w == 0) ? wqp : (w == 1) ? wkp : wvp;
        i = b2 * 256 + threadIdx.x; arole = false;
    }
    const int idx = i * 4;
    const int row = idx >> 10, k = idx & 1023;
    float4 v = *(const float4*)(src + idx);
    float f[4] = {v.x, v.y, v.z, v.w};
    uint32_t hp[2], lp[2];
#pragma unroll
    for (int j = 0; j < 2; j++) {
        bf16 h0, l0, h1, l1;
        split1(f[2 * j], h0, l0); split1(f[2 * j + 1], h1, l1);
        hp[j] = ((uint32_t)__bfloat16_as_ushort(h1) << 16) | __bfloat16_as_ushort(h0);
        lp[j] = ((uint32_t)__bfloat16_as_ushort(l1) << 16) | __bfloat16_as_ushort(l0);
    }
    if (arole) {
        size_t off = ((size_t)(row >> 7) * 32 + (k >> 5)) * PANEL_A
                   + chunk_off(row & 127, (k & 31) >> 3) + (k & 7) * 2;
        *(uint2*)(dst + off)        = make_uint2(hp[0], hp[1]);
        *(uint2*)(dst + off + 8192) = make_uint2(lp[0], lp[1]);
    } else {
        size_t off = ((size_t)(row >> 8) * 32 + (k >> 5)) * PANEL_B
                   + chunk_off(row & 255, (k & 31) >> 3) + (k & 7) * 2;
        *(uint2*)(dst + off)         = make_uint2(hp[0], hp[1]);
        *(uint2*)(dst + off + 16384) = make_uint2(lp[0], lp[1]);
    }
}

// ---------------------------------------------------------------------------
// GEMM kernels
// ---------------------------------------------------------------------------
__global__ void __launch_bounds__(NTHREADS, 1) qkv_tc(
    const float* __restrict__ bq, const float* __restrict__ bk, const float* __restrict__ bv)
{
    const int m0 = blockIdx.y * 128;
    const int n0 = blockIdx.x * 256;
    if (blockIdx.z == 0) {
        gemm_core<0, 32, 0>(g_xp, g_wqp, HDIM, bq, g_qp, nullptr, HDIM, m0, n0, 0);
    } else if (blockIdx.z == 1) {
        gemm_core<1, 32, 0>(g_xp, g_wkp, HDIM, bk, g_kp, nullptr, HDIM, m0, n0, 0);
    } else {
        const int b = m0 >> 11;
        gemm_core<3, 32, 0>(g_xp, g_wvp, HDIM, bv,
                            g_vtp + (size_t)b * 4 * 64 * PANEL_B, nullptr, SEQ,
                            m0, n0, m0 & (SEQ - 1));
    }
}

// Split-K=2 over HDIM: z = half*BATCH + b. Half 0 -> g_p (panels 0..15),
// half 1 -> g_p2 (panels 16..31). Partials summed in softmax.
__global__ void __launch_bounds__(NTHREADS, 1) scores_tc()
{
    const int z = blockIdx.z;
    const int b = z & (BATCH - 1), half = z >> 2;
    const char* qp = g_qp + (size_t)b * 16 * 32 * PANEL_A;
    const char* kp = g_kp + (size_t)b * 8 * 32 * PANEL_B;
    const int m0 = blockIdx.y * 128, n0 = blockIdx.x * 256;
    if (half == 0) {
        gemm_core<2, 32, 0>(qp, kp, HDIM / 2, nullptr, nullptr,
                            g_p + (size_t)b * SEQ * SEQ, SEQ, m0, n0, 0);
    } else {
        gemm_core<2, 32, 16>(qp, kp, HDIM / 2, nullptr, nullptr,
                             g_p2 + (size_t)b * SEQ * SEQ, SEQ, m0, n0, 0);
    }
}

__global__ void __launch_bounds__(NTHREADS, 1) context_tc(float* __restrict__ ctx)
{
    const int b = blockIdx.z;
    gemm_core<2, 64, 0>(g_pp + (size_t)b * 16 * 64 * PANEL_A,
                        g_vtp + (size_t)b * 4 * 64 * PANEL_B,
                        SEQ, nullptr, nullptr,
                        ctx + (size_t)b * SEQ * HDIM, HDIM,
                        blockIdx.y * 128, blockIdx.x * 256, 0);
}

// ---------------------------------------------------------------------------
// Softmax: sum split-K partials, softmax, split probs into A-role panels
// ---------------------------------------------------------------------------
__global__ void __launch_bounds__(256) softmax_kernel()
{
    const int row = blockIdx.x;
    const float4* p4 = (const float4*)(g_p  + (size_t)row * SEQ) + threadIdx.x * 2;
    const float4* q4 = (const float4*)(g_p2 + (size_t)row * SEQ) + threadIdx.x * 2;
    const int tid = threadIdx.x;

    float4 va = p4[0], vb = p4[1];
    float4 wa = q4[0], wb = q4[1];
    float v[8] = {va.x + wa.x, va.y + wa.y, va.z + wa.z, va.w + wa.w,
                  vb.x + wb.x, vb.y + wb.y, vb.z + wb.z, vb.w + wb.w};
    float m = v[0];
#pragma unroll
    for (int i = 1; i < 8; i++) m = fmaxf(m, v[i]);

    __shared__ float red[8];
#pragma unroll
    for (int o = 16; o; o >>= 1) m = fmaxf(m, __shfl_xor_sync(0xffffffffu, m, o));
    if ((tid & 31) == 0) red[tid >> 5] = m;
    __syncthreads();
    m = red[0];
#pragma unroll
    for (int i = 1; i < 8; i++) m = fmaxf(m, red[i]);
    __syncthreads();

    float s = 0.f;
#pragma unroll
    for (int i = 0; i < 8; i++) {
        v[i] = __expf(v[i] - m);
        s += v[i];
    }
#pragma unroll
    for (int o = 16; o; o >>= 1) s += __shfl_xor_sync(0xffffffffu, s, o);
    if ((tid & 31) == 0) red[tid >> 5] = s;
    __syncthreads();
    float tot = 0.f;
#pragma unroll
    for (int i = 0; i < 8; i++) tot += red[i];
    const float inv = 1.0f / tot;

    // 8 consecutive cols per thread -> one 16B h-store + one 16B l-store
    uint32_t hp[4], lp[4];
#pragma unroll
    for (int j = 0; j < 4; j++) {
        bf16 h0, l0, h1, l1;
        split1(v[2 * j] * inv, h0, l0);
        split1(v[2 * j + 1] * inv, h1, l1);
        hp[j] = ((uint32_t)__bfloat16_as_ushort(h1) << 16) | __bfloat16_as_ushort(h0);
        lp[j] = ((uint32_t)__bfloat16_as_ushort(l1) << 16) | __bfloat16_as_ushort(l0);
    }
    const int col0 = tid * 8;
    const size_t off = ((size_t)(row >> 7) * 64 + (col0 >> 5)) * PANEL_A
                     + chunk_off(row & 127, (col0 & 31) >> 3);
    *(uint4*)(g_pp + off)        = make_uint4(hp[0], hp[1], hp[2], hp[3]);
    *(uint4*)(g_pp + off + 8192) = make_uint4(lp[0], lp[1], lp[2], lp[3]);
}

// ---------------------------------------------------------------------------
// Column sums of probs, per-panel reduction
// ---------------------------------------------------------------------------
__global__ void __launch_bounds__(256) colsum_kernel(float* __restrict__ out)
{
    const int pk = blockIdx.x;   // 0..63 k-panel
    const int pr = blockIdx.y;   // 0..63 row-panel
    const char* panel = g_pp + ((size_t)pr * 64 + pk) * PANEL_A;
    const int tid = threadIdx.x;
    const int col = tid & 31;
    const int rg  = tid >> 5;    // 8 groups of 16 rows

    const uint32_t cbase = ((col & 31) >> 3) * 128 + (col & 7) * 2;
    float s = 0.f;
#pragma unroll
    for (int r = rg * 16; r < rg * 16 + 16; r++) {
        uint32_t off = (uint32_t)((r & 7) * 16 + 4 * (r >> 3) * 128) + cbase;
        s += __bfloat162float(*(const bf16*)(panel + off))
           + __bfloat162float(*(const bf16*)(panel + off + 8192));
    }
    __shared__ float part[256];
    part[tid] = s;
    __syncthreads();
    if (tid < 32) {
        float t = 0.f;
#pragma unroll
        for (int j = 0; j < 8; j++) t += part[tid + 32 * j];
        const int batch = pr >> 4;
        atomicAdd(out + batch * SEQ + pk * 32 + tid, t);
    }
}

// ---------------------------------------------------------------------------
extern "C" void kernel_launch(void* const* d_in, const int* in_sizes, int n_in,
                              void* d_out, int out_size)
{
    const float* x  = (const float*)d_in[0];
    const float* Wq = (const float*)d_in[1];
    const float* bq = (const float*)d_in[2];
    const float* Wk = (const float*)d_in[3];
    const float* bk = (const float*)d_in[4];
    const float* Wv = (const float*)d_in[5];
    const float* bv = (const float*)d_in[6];

    float* ctx = (float*)d_out;
    float* sc  = ctx + (size_t)BATCH * SEQ * HDIM;

    cudaFuncSetAttribute((const void*)qkv_tc,
                         cudaFuncAttributeMaxDynamicSharedMemorySize, SMEM_BYTES);
    cudaFuncSetAttribute((const void*)scores_tc,
                         cudaFuncAttributeMaxDynamicSharedMemorySize, SMEM_BYTES);
    cudaFuncSetAttribute((const void*)context_tc,
                         cudaFuncAttributeMaxDynamicSharedMemorySize, SMEM_BYTES);

    char *xp, *wqp, *wkp, *wvp;
    cudaGetSymbolAddress((void**)&xp,  g_xp);
    cudaGetSymbolAddress((void**)&wqp, g_wqp);
    cudaGetSymbolAddress((void**)&wkp, g_wkp);
    cudaGetSymbolAddress((void**)&wvp, g_wvp);

    cudaMemsetAsync(sc, 0, (size_t)BATCH * SEQ * sizeof(float));

    split_fused<<<8192 + 3 * 1024, 256>>>(x, Wq, Wk, Wv, xp, wqp, wkp, wvp);

    qkv_tc<<<dim3(HDIM / 256, MTOT / 128, 3), NTHREADS, SMEM_BYTES>>>(bq, bk, bv);
    scores_tc<<<dim3(SEQ / 256, SEQ / 128, BATCH * 2), NTHREADS, SMEM_BYTES>>>();
    softmax_kernel<<<MTOT, 256>>>();
    colsum_kernel<<<dim3(64, 64), 256>>>(sc);
    context_tc<<<dim3(HDIM / 256, SEQ / 128, BATCH), NTHREADS, SMEM_BYTES>>>(ctx);
}

// round 14
// speedup vs baseline: 1.0165x; 1.0021x over previous
#include <cuda_runtime.h>
#include <cuda_bf16.h>
#include <stdint.h>

#define HDIM 1024
#define SEQ  2048
#define BATCH 4
#define MTOT (BATCH * SEQ)

typedef __nv_bfloat16 bf16;

// ---------------------------------------------------------------------------
// Panel geometry
// A-role panels: 128 rows x 32 k, [h 8KB | l 8KB] = 16KB
// B-role panels: 256 rows x 32 k, [h 16KB | l 16KB] = 32KB
// Within each half: 16B chunk (r, cc) at (r&7)*16 + (cc + 4*(r>>3))*128
// ---------------------------------------------------------------------------
#define PANEL_A 16384
#define PANEL_B 32768

// Scratch (__device__ globals: allocation-free rule)
__device__ __align__(128) char g_xp [(size_t)64 * 32 * PANEL_A];            // x   A-role
__device__ __align__(128) char g_wqp[(size_t)4  * 32 * PANEL_B];            // Wq  B-role
__device__ __align__(128) char g_wkp[(size_t)4  * 32 * PANEL_B];
__device__ __align__(128) char g_wvp[(size_t)4  * 32 * PANEL_B];
__device__ __align__(128) char g_qp [(size_t)64 * 32 * PANEL_A];            // Q   A-role
__device__ __align__(128) char g_kp [(size_t)32 * 32 * PANEL_B];            // K   B-role
__device__ __align__(128) char g_vtp[(size_t)BATCH * 4 * 64 * PANEL_B];     // V^T B-role
__device__ float g_p [(size_t)BATCH * SEQ * SEQ];                           // logits partial 0
__device__ float g_p2[(size_t)BATCH * SEQ * SEQ];                           // logits partial 1
__device__ __align__(128) char g_pp [(size_t)64 * 64 * PANEL_A];            // probs A-role

// ---------------------------------------------------------------------------
// Helpers
// ---------------------------------------------------------------------------
__device__ __forceinline__ uint32_t smem_u32(const void* p) {
    uint32_t a;
    asm("{ .reg .u64 t; cvta.to.shared.u64 t, %1; cvt.u32.u64 %0, t; }" : "=r"(a) : "l"(p));
    return a;
}

__device__ __forceinline__ void ldsm4(uint32_t* r, uint32_t addr) {
    asm volatile("ldmatrix.sync.aligned.m8n8.x4.shared.b16 {%0,%1,%2,%3}, [%4];"
                 : "=r"(r[0]), "=r"(r[1]), "=r"(r[2]), "=r"(r[3]) : "r"(addr));
}

__device__ __forceinline__ void mma16816(float* d, const uint32_t* a, uint32_t b0, uint32_t b1) {
    asm volatile("mma.sync.aligned.m16n8k16.row.col.f32.bf16.bf16.f32 "
                 "{%0,%1,%2,%3}, {%4,%5,%6,%7}, {%8,%9}, {%0,%1,%2,%3};"
                 : "+f"(d[0]), "+f"(d[1]), "+f"(d[2]), "+f"(d[3])
                 : "r"(a[0]), "r"(a[1]), "r"(a[2]), "r"(a[3]), "r"(b0), "r"(b1));
}

__device__ __forceinline__ void bulk_g2s(uint32_t dst, const void* src, uint32_t bytes, uint32_t mbar) {
    asm volatile("cp.async.bulk.shared::cluster.global.mbarrier::complete_tx::bytes "
                 "[%0], [%1], %2, [%3];"
                 :: "r"(dst), "l"(src), "r"(bytes), "r"(mbar) : "memory");
}

#define MBAR_INIT(addr, cnt) \
    asm volatile("mbarrier.init.shared.b64 [%0], %1;" :: "r"(addr), "r"(cnt) : "memory")
#define MBAR_EXPECT_TX(addr, tx) \
    asm volatile("mbarrier.arrive.expect_tx.shared::cta.b64 _, [%0], %1;" :: "r"(addr), "r"(tx) : "memory")
#define FENCE_ASYNC_SHARED() asm volatile("fence.proxy.async.shared::cta;" ::: "memory")

#define MBAR_WAIT_PARITY(addr, par) do {                                             \
    uint32_t _mbar = (uint32_t)(addr);                                               \
    uint32_t _par  = (uint32_t)(par);                                                \
    uint32_t _done;                                                                  \
    asm volatile("{\n\t.reg .pred p;\n\t"                                            \
        "mbarrier.try_wait.parity.acquire.cta.shared::cta.b64 p, [%1], %2;\n\t"      \
        "selp.b32 %0, 1, 0, p;\n\t}"                                                 \
        : "=r"(_done) : "r"(_mbar), "r"(_par) : "memory");                           \
    if (!_done) {                                                                    \
        asm volatile("{\n\t.reg .pred P1;\n\t"                                       \
            "WAIT_LOOP_%=:\n\t"                                                      \
            "mbarrier.try_wait.parity.acquire.cta.shared::cta.b64 P1, [%0], %1, 0x989680;\n\t" \
            "@P1 bra.uni WAIT_DONE_%=;\n\t"                                          \
            "bra.uni WAIT_LOOP_%=;\n\t"                                              \
            "WAIT_DONE_%=:\n\t}"                                                     \
            :: "r"(_mbar), "r"(_par) : "memory");                                    \
    }                                                                                \
} while (0)

__device__ __forceinline__ void split1(float v, bf16& h, bf16& l) {
    h = __float2bfloat16_rn(v);
    l = __float2bfloat16_rn(v - __bfloat162float(h));
}

__device__ __host__ __forceinline__ uint32_t chunk_off(int r, int cc) {
    return (uint32_t)((r & 7) * 16 + (cc + 4 * (r >> 3)) * 128);
}

// ---------------------------------------------------------------------------
// GEMM: C[m0+i, n0+j] = sum_k A[m0+i,k]*B[n0+j,k], pre-packed panel operands.
// CTA 128x256, 16 warps (4m x 4n) of 32x64, BK=32, 4-stage bulk-copy ring.
// Stage layout: [Ah 8K][Al 8K][Bh 16K][Bl 16K] = 48KB.
// FROZEN inner loop (R11: ~97% of legacy-HMMA rate ceiling).
// ---------------------------------------------------------------------------
#define STAGE_BYTES 49152
#define NSTAGE 4
#define SMEM_BYTES (1024 + NSTAGE * STAGE_BYTES)   // 197632
#define NTHREADS 512

// MODE 0: A-role split panels +bias | 1: B-role split panels +bias
// MODE 2: fp32 row store            | 3: B-role transposed split panels +bias
template <int MODE, int NCT, int C0>
__device__ __forceinline__ void gemm_core(
    const char* __restrict__ Ap, const char* __restrict__ Bp,
    int K, const float* __restrict__ bias,
    char* __restrict__ outp, float* __restrict__ outf,
    int ldc, int m0, int n0, int cm0)
{
    extern __shared__ char smem[];
    const uint32_t sb = smem_u32(smem);
    const int tid = threadIdx.x, lane = tid & 31, wid = tid >> 5;
    const int wm = wid & 3, wn = wid >> 2;   // 4 x 4 warps, warp tile 32 x 64

    float acc[2][8][4];
#pragma unroll
    for (int i = 0; i < 2; i++)
#pragma unroll
        for (int j = 0; j < 8; j++)
#pragma unroll
            for (int e = 0; e < 4; e++) acc[i][j][e] = 0.f;

    const int NC = K >> 5;
    const size_t a_base = (size_t)(m0 >> 7) * NCT + C0;
    const size_t b_base = (size_t)(n0 >> 8) * NCT + C0;

    if (tid == 0) {
#pragma unroll
        for (int s = 0; s < NSTAGE; s++) MBAR_INIT(sb + s * 8, 1);
    }
    __syncthreads();
    FENCE_ASYNC_SHARED();

    auto issue = [&](int s) {
        const uint32_t mb  = sb + (uint32_t)(s & 3) * 8;
        const uint32_t dst = sb + 1024 + (uint32_t)(s & 3) * STAGE_BYTES;
        MBAR_EXPECT_TX(mb, (uint32_t)STAGE_BYTES);
        bulk_g2s(dst,           Ap + (a_base + s) * PANEL_A, PANEL_A, mb);
        bulk_g2s(dst + PANEL_A, Bp + (b_base + s) * PANEL_B, PANEL_B, mb);
    };

    if (tid == 0) { issue(0); issue(1); issue(2); }

    const uint32_t lsel = (lane & 7) * 16 + (lane >> 4) * 128 + ((lane >> 3) & 1) * 512;

#pragma unroll 1
    for (int c = 0; c < NC; c++) {
        MBAR_WAIT_PARITY(sb + (c & 3) * 8, (c >> 2) & 1);
        __syncthreads();
        if (tid == 0 && c + 3 < NC) issue(c + 3);

        const uint32_t base = sb + 1024 + (uint32_t)(c & 3) * STAGE_BYTES;

#pragma unroll
        for (int ks = 0; ks < 2; ks++) {
            const uint32_t koff = (uint32_t)ks * 256;
            uint32_t ah[2][4], al[2][4];
#pragma unroll
            for (int mi = 0; mi < 2; mi++) {
                uint32_t g = (uint32_t)(wm * 4 + mi * 2);
                uint32_t off = base + lsel + koff + g * 512;
                ldsm4(ah[mi], off);
                ldsm4(al[mi], off + 8192);
            }
#pragma unroll
            for (int bi = 0; bi < 4; bi++) {
                uint32_t g = (uint32_t)(wn * 8 + bi * 2);
                uint32_t off = base + 16384 + lsel + koff + g * 512;
                uint32_t bh[4], bl[4];
                ldsm4(bh, off);
                ldsm4(bl, off + 16384);
#pragma unroll
                for (int mi = 0; mi < 2; mi++)
#pragma unroll
                    for (int j = 0; j < 2; j++) {
                        const int ni = bi * 2 + j;
                        mma16816(acc[mi][ni], ah[mi], bh[j], bh[j + 2]);
                        mma16816(acc[mi][ni], ah[mi], bl[j], bl[j + 2]);
                        mma16816(acc[mi][ni], al[mi], bh[j], bh[j + 2]);
                    }
            }
        }
    }

    // epilogue — C frag: rows (lane>>2)+{0,8}, cols 2*(lane&3)+{0,1}
    const int rl = lane >> 2, cl = (lane & 3) * 2;
#pragma unroll
    for (int mi = 0; mi < 2; mi++)
#pragma unroll
        for (int ni = 0; ni < 8; ni++) {
            const int col = n0 + wn * 64 + ni * 8 + cl;
#pragma unroll
            for (int rh = 0; rh < 2; rh++) {
                float v0 = acc[mi][ni][rh * 2 + 0];
                float v1 = acc[mi][ni][rh * 2 + 1];
                if (MODE != 2) {
                    v0 += __ldg(bias + col);
                    v1 += __ldg(bias + col + 1);
                }
                const int row = m0 + wm * 32 + mi * 16 + rl + rh * 8;
                if (MODE == 2) {
                    float2 o = {v0, v1};
                    *(float2*)(outf + (size_t)row * ldc + col) = o;
                } else if (MODE == 0) {   // A-role panels, k-width = ldc
                    bf16 h0, l0, h1, l1;
                    split1(v0, h0, l0); split1(v1, h1, l1);
                    uint32_t hp = ((uint32_t)__bfloat16_as_ushort(h1) << 16) | __bfloat16_as_ushort(h0);
                    uint32_t lp = ((uint32_t)__bfloat16_as_ushort(l1) << 16) | __bfloat16_as_ushort(l0);
                    size_t off = ((size_t)(row >> 7) * (ldc >> 5) + (col >> 5)) * PANEL_A
                               + chunk_off(row & 127, (col & 31) >> 3) + (col & 7) * 2;
                    *(uint32_t*)(outp + off)        = hp;
                    *(uint32_t*)(outp + off + 8192) = lp;
                } else if (MODE == 1) {   // B-role panels, k-width = ldc
                    bf16 h0, l0, h1, l1;
                    split1(v0, h0, l0); split1(v1, h1, l1);
                    uint32_t hp = ((uint32_t)__bfloat16_as_ushort(h1) << 16) | __bfloat16_as_ushort(h0);
                    uint32_t lp = ((uint32_t)__bfloat16_as_ushort(l1) << 16) | __bfloat16_as_ushort(l0);
                    size_t off = ((size_t)(row >> 8) * (ldc >> 5) + (col >> 5)) * PANEL_B
                               + chunk_off(row & 255, (col & 31) >> 3) + (col & 7) * 2;
                    *(uint32_t*)(outp + off)         = hp;
                    *(uint32_t*)(outp + off + 16384) = lp;
                } else {                  // MODE 3: V^T, B-role rows = col(h), k = local seq
                    const int mloc = cm0 + wm * 32 + mi * 16 + rl + rh * 8;
                    bf16 h0, l0, h1, l1;
                    split1(v0, h0, l0); split1(v1, h1, l1);
                    size_t pb = ((size_t)(col >> 8) * (SEQ >> 5) + (mloc >> 5)) * PANEL_B;
                    uint32_t co0 = chunk_off(col & 255, (mloc & 31) >> 3) + (mloc & 7) * 2;
                    uint32_t co1 = chunk_off((col + 1) & 255, (mloc & 31) >> 3) + (mloc & 7) * 2;
                    *(bf16*)(outp + pb + co0)         = h0;
                    *(bf16*)(outp + pb + co0 + 16384) = l0;
                    *(bf16*)(outp + pb + co1)         = h1;
                    *(bf16*)(outp + pb + co1 + 16384) = l1;
                }
            }
        }
}

// ---------------------------------------------------------------------------
// Fused split: one launch packs x (A-role) + Wq/Wk/Wv (B-role)
// ---------------------------------------------------------------------------
__global__ void __launch_bounds__(256) split_fused(
    const float* __restrict__ x, const float* __restrict__ Wq,
    const float* __restrict__ Wk, const float* __restrict__ Wv,
    char* __restrict__ xp, char* __restrict__ wqp,
    char* __restrict__ wkp, char* __restrict__ wvp)
{
    const int bid = blockIdx.x;
    const float* src;
    char* dst;
    int i;
    bool arole;
    if (bid < 8192) {            // x: 8192x1024 fp32, A-role
        src = x; dst = xp; i = bid * 256 + threadIdx.x; arole = true;
    } else {
        const int w = (bid - 8192) >> 10;
        const int b2 = (bid - 8192) & 1023;
        src = (w == 0) ? Wq : (w == 1) ? Wk : Wv;
        dst = (w == 0) ? wqp : (w == 1) ? wkp : wvp;
        i = b2 * 256 + threadIdx.x; arole = false;
    }
    const int idx = i * 4;
    const int row = idx >> 10, k = idx & 1023;
    float4 v = *(const float4*)(src + idx);
    float f[4] = {v.x, v.y, v.z, v.w};
    uint32_t hp[2], lp[2];
#pragma unroll
    for (int j = 0; j < 2; j++) {
        bf16 h0, l0, h1, l1;
        split1(f[2 * j], h0, l0); split1(f[2 * j + 1], h1, l1);
        hp[j] = ((uint32_t)__bfloat16_as_ushort(h1) << 16) | __bfloat16_as_ushort(h0);
        lp[j] = ((uint32_t)__bfloat16_as_ushort(l1) << 16) | __bfloat16_as_ushort(l0);
    }
    if (arole) {
        size_t off = ((size_t)(row >> 7) * 32 + (k >> 5)) * PANEL_A
                   + chunk_off(row & 127, (k & 31) >> 3) + (k & 7) * 2;
        *(uint2*)(dst + off)        = make_uint2(hp[0], hp[1]);
        *(uint2*)(dst + off + 8192) = make_uint2(lp[0], lp[1]);
    } else {
        size_t off = ((size_t)(row >> 8) * 32 + (k >> 5)) * PANEL_B
                   + chunk_off(row & 255, (k & 31) >> 3) + (k & 7) * 2;
        *(uint2*)(dst + off)         = make_uint2(hp[0], hp[1]);
        *(uint2*)(dst + off + 16384) = make_uint2(lp[0], lp[1]);
    }
}

// ---------------------------------------------------------------------------
// GEMM kernels
// ---------------------------------------------------------------------------
// Q/K projections only (V moved to its own launch on a second stream).
__global__ void __launch_bounds__(NTHREADS, 1) qkv_qk_tc(
    const float* __restrict__ bq, const float* __restrict__ bk)
{
    const int m0 = blockIdx.y * 128;
    const int n0 = blockIdx.x * 256;
    if (blockIdx.z == 0) {
        gemm_core<0, 32, 0>(g_xp, g_wqp, HDIM, bq, g_qp, nullptr, HDIM, m0, n0, 0);
    } else {
        gemm_core<1, 32, 0>(g_xp, g_wkp, HDIM, bk, g_kp, nullptr, HDIM, m0, n0, 0);
    }
}

// V^T projection — independent of scores/softmax; runs on stream 2.
__global__ void __launch_bounds__(NTHREADS, 1) vt_tc(const float* __restrict__ bv)
{
    const int m0 = blockIdx.y * 128;
    const int n0 = blockIdx.x * 256;
    const int b = m0 >> 11;
    gemm_core<3, 32, 0>(g_xp, g_wvp, HDIM, bv,
                        g_vtp + (size_t)b * 4 * 64 * PANEL_B, nullptr, SEQ,
                        m0, n0, m0 & (SEQ - 1));
}

// Split-K=2 over HDIM: z = half*BATCH + b. Half 0 -> g_p, half 1 -> g_p2.
__global__ void __launch_bounds__(NTHREADS, 1) scores_tc()
{
    const int z = blockIdx.z;
    const int b = z & (BATCH - 1), half = z >> 2;
    const char* qp = g_qp + (size_t)b * 16 * 32 * PANEL_A;
    const char* kp = g_kp + (size_t)b * 8 * 32 * PANEL_B;
    const int m0 = blockIdx.y * 128, n0 = blockIdx.x * 256;
    if (half == 0) {
        gemm_core<2, 32, 0>(qp, kp, HDIM / 2, nullptr, nullptr,
                            g_p + (size_t)b * SEQ * SEQ, SEQ, m0, n0, 0);
    } else {
        gemm_core<2, 32, 16>(qp, kp, HDIM / 2, nullptr, nullptr,
                             g_p2 + (size_t)b * SEQ * SEQ, SEQ, m0, n0, 0);
    }
}

__global__ void __launch_bounds__(NTHREADS, 1) context_tc(float* __restrict__ ctx)
{
    const int b = blockIdx.z;
    gemm_core<2, 64, 0>(g_pp + (size_t)b * 16 * 64 * PANEL_A,
                        g_vtp + (size_t)b * 4 * 64 * PANEL_B,
                        SEQ, nullptr, nullptr,
                        ctx + (size_t)b * SEQ * HDIM, HDIM,
                        blockIdx.y * 128, blockIdx.x * 256, 0);
}

// ---------------------------------------------------------------------------
// Softmax: sum split-K partials, softmax, split probs into A-role panels
// ---------------------------------------------------------------------------
__global__ void __launch_bounds__(256) softmax_kernel()
{
    const int row = blockIdx.x;
    const float4* p4 = (const float4*)(g_p  + (size_t)row * SEQ) + threadIdx.x * 2;
    const float4* q4 = (const float4*)(g_p2 + (size_t)row * SEQ) + threadIdx.x * 2;
    const int tid = threadIdx.x;

    float4 va = p4[0], vb = p4[1];
    float4 wa = q4[0], wb = q4[1];
    float v[8] = {va.x + wa.x, va.y + wa.y, va.z + wa.z, va.w + wa.w,
                  vb.x + wb.x, vb.y + wb.y, vb.z + wb.z, vb.w + wb.w};
    float m = v[0];
#pragma unroll
    for (int i = 1; i < 8; i++) m = fmaxf(m, v[i]);

    __shared__ float red[8];
#pragma unroll
    for (int o = 16; o; o >>= 1) m = fmaxf(m, __shfl_xor_sync(0xffffffffu, m, o));
    if ((tid & 31) == 0) red[tid >> 5] = m;
    __syncthreads();
    m = red[0];
#pragma unroll
    for (int i = 1; i < 8; i++) m = fmaxf(m, red[i]);
    __syncthreads();

    float s = 0.f;
#pragma unroll
    for (int i = 0; i < 8; i++) {
        v[i] = __expf(v[i] - m);
        s += v[i];
    }
#pragma unroll
    for (int o = 16; o; o >>= 1) s += __shfl_xor_sync(0xffffffffu, s, o);
    if ((tid & 31) == 0) red[tid >> 5] = s;
    __syncthreads();
    float tot = 0.f;
#pragma unroll
    for (int i = 0; i < 8; i++) tot += red[i];
    const float inv = 1.0f / tot;

    uint32_t hp[4], lp[4];
#pragma unroll
    for (int j = 0; j < 4; j++) {
        bf16 h0, l0, h1, l1;
        split1(v[2 * j] * inv, h0, l0);
        split1(v[2 * j + 1] * inv, h1, l1);
        hp[j] = ((uint32_t)__bfloat16_as_ushort(h1) << 16) | __bfloat16_as_ushort(h0);
        lp[j] = ((uint32_t)__bfloat16_as_ushort(l1) << 16) | __bfloat16_as_ushort(l0);
    }
    const int col0 = tid * 8;
    const size_t off = ((size_t)(row >> 7) * 64 + (col0 >> 5)) * PANEL_A
                     + chunk_off(row & 127, (col0 & 31) >> 3);
    *(uint4*)(g_pp + off)        = make_uint4(hp[0], hp[1], hp[2], hp[3]);
    *(uint4*)(g_pp + off + 8192) = make_uint4(lp[0], lp[1], lp[2], lp[3]);
}

// ---------------------------------------------------------------------------
// Column sums of probs, per-panel reduction
// ---------------------------------------------------------------------------
__global__ void __launch_bounds__(256) colsum_kernel(float* __restrict__ out)
{
    const int pk = blockIdx.x;   // 0..63 k-panel
    const int pr = blockIdx.y;   // 0..63 row-panel
    const char* panel = g_pp + ((size_t)pr * 64 + pk) * PANEL_A;
    const int tid = threadIdx.x;
    const int col = tid & 31;
    const int rg  = tid >> 5;    // 8 groups of 16 rows

    const uint32_t cbase = ((col & 31) >> 3) * 128 + (col & 7) * 2;
    float s = 0.f;
#pragma unroll
    for (int r = rg * 16; r < rg * 16 + 16; r++) {
        uint32_t off = (uint32_t)((r & 7) * 16 + 4 * (r >> 3) * 128) + cbase;
        s += __bfloat162float(*(const bf16*)(panel + off))
           + __bfloat162float(*(const bf16*)(panel + off + 8192));
    }
    __shared__ float part[256];
    part[tid] = s;
    __syncthreads();
    if (tid < 32) {
        float t = 0.f;
#pragma unroll
        for (int j = 0; j < 8; j++) t += part[tid + 32 * j];
        const int batch = pr >> 4;
        atomicAdd(out + batch * SEQ + pk * 32 + tid, t);
    }
}

// ---------------------------------------------------------------------------
extern "C" void kernel_launch(void* const* d_in, const int* in_sizes, int n_in,
                              void* d_out, int out_size)
{
    const float* x  = (const float*)d_in[0];
    const float* Wq = (const float*)d_in[1];
    const float* bq = (const float*)d_in[2];
    const float* Wk = (const float*)d_in[3];
    const float* bk = (const float*)d_in[4];
    const float* Wv = (const float*)d_in[5];
    const float* bv = (const float*)d_in[6];

    float* ctx = (float*)d_out;
    float* sc  = ctx + (size_t)BATCH * SEQ * HDIM;

    cudaFuncSetAttribute((const void*)qkv_qk_tc,
                         cudaFuncAttributeMaxDynamicSharedMemorySize, SMEM_BYTES);
    cudaFuncSetAttribute((const void*)vt_tc,
                         cudaFuncAttributeMaxDynamicSharedMemorySize, SMEM_BYTES);
    cudaFuncSetAttribute((const void*)scores_tc,
                         cudaFuncAttributeMaxDynamicSharedMemorySize, SMEM_BYTES);
    cudaFuncSetAttribute((const void*)context_tc,
                         cudaFuncAttributeMaxDynamicSharedMemorySize, SMEM_BYTES);

    char *xp, *wqp, *wkp, *wvp;
    cudaGetSymbolAddress((void**)&xp,  g_xp);
    cudaGetSymbolAddress((void**)&wqp, g_wqp);
    cudaGetSymbolAddress((void**)&wkp, g_wkp);
    cudaGetSymbolAddress((void**)&wvp, g_wvp);

    // Lazily create the second stream + fork/join events ONCE (first call is
    // the uncaptured correctness run; captured calls only record/wait).
    static cudaStream_t s2 = nullptr;
    static cudaEvent_t evFork = nullptr, evJoin = nullptr;
    if (s2 == nullptr) {
        cudaStreamCreateWithFlags(&s2, cudaStreamNonBlocking);
        cudaEventCreateWithFlags(&evFork, cudaEventDisableTiming);
        cudaEventCreateWithFlags(&evJoin, cudaEventDisableTiming);
    }

    cudaMemsetAsync(sc, 0, (size_t)BATCH * SEQ * sizeof(float));

    split_fused<<<8192 + 3 * 1024, 256>>>(x, Wq, Wk, Wv, xp, wqp, wkp, wvp);

    // Fork: V^T projection on stream 2 (depends only on split_fused)
    cudaEventRecord(evFork, 0);
    cudaStreamWaitEvent(s2, evFork, 0);
    vt_tc<<<dim3(HDIM / 256, MTOT / 128), NTHREADS, SMEM_BYTES, s2>>>(bv);
    cudaEventRecord(evJoin, s2);

    // Main stream: Q/K projections -> scores -> softmax -> colsum
    qkv_qk_tc<<<dim3(HDIM / 256, MTOT / 128, 2), NTHREADS, SMEM_BYTES>>>(bq, bk);
    scores_tc<<<dim3(SEQ / 256, SEQ / 128, BATCH * 2), NTHREADS, SMEM_BYTES>>>();
    softmax_kernel<<<MTOT, 256>>>();
    colsum_kernel<<<dim3(64, 64), 256>>>(sc);

    // Join: context needs V^T
    cudaStreamWaitEvent(0, evJoin, 0);
    context_tc<<<dim3(HDIM / 256, SEQ / 128, BATCH), NTHREADS, SMEM_BYTES>>>(ctx);
}

// round 15
// speedup vs baseline: 1.2423x; 1.2222x over previous
#include <cuda_runtime.h>
#include <cuda_bf16.h>
#include <cuda_fp16.h>
#include <stdint.h>

#define HDIM 1024
#define SEQ  2048
#define BATCH 4
#define MTOT (BATCH * SEQ)

typedef __nv_bfloat16 bf16;

// ---------------------------------------------------------------------------
// Panel geometry
// A-role panels: 128 rows x 32 k, [h 8KB | l 8KB] = 16KB (bf16 split)
// B-role panels: 256 rows x 32 k, [h 16KB | l 16KB] = 32KB (bf16 split)
// fp16 h-only: A-role 8KB, B-role 16KB (same chunk layout, hi half only)
// Within each half: 16B chunk (r, cc) at (r&7)*16 + (cc + 4*(r>>3))*128
// ---------------------------------------------------------------------------
#define PANEL_A 16384
#define PANEL_B 32768
#define PANEL_AH 8192
#define PANEL_BH 16384

// Scratch (__device__ globals: allocation-free rule)
__device__ __align__(128) char g_xp [(size_t)64 * 32 * PANEL_A];            // x   A-role bf16
__device__ __align__(128) char g_wqp[(size_t)4  * 32 * PANEL_B];            // Wq  B-role bf16
__device__ __align__(128) char g_wkp[(size_t)4  * 32 * PANEL_B];
__device__ __align__(128) char g_wvp[(size_t)4  * 32 * PANEL_B];
__device__ __align__(128) char g_qp [(size_t)64 * 32 * PANEL_A];            // Q   A-role bf16
__device__ __align__(128) char g_kp [(size_t)32 * 32 * PANEL_B];            // K   B-role bf16
__device__ __align__(128) char g_vthp[(size_t)BATCH * 4 * 64 * PANEL_BH];   // V^T B-role fp16 h
__device__ float g_p [(size_t)BATCH * SEQ * SEQ];                           // logits partial 0
__device__ float g_p2[(size_t)BATCH * SEQ * SEQ];                           // logits partial 1
__device__ __align__(128) char g_pph[(size_t)64 * 64 * PANEL_AH];           // probs A-role fp16 h

// ---------------------------------------------------------------------------
// Helpers
// ---------------------------------------------------------------------------
__device__ __forceinline__ uint32_t smem_u32(const void* p) {
    uint32_t a;
    asm("{ .reg .u64 t; cvta.to.shared.u64 t, %1; cvt.u32.u64 %0, t; }" : "=r"(a) : "l"(p));
    return a;
}

__device__ __forceinline__ void ldsm4(uint32_t* r, uint32_t addr) {
    asm volatile("ldmatrix.sync.aligned.m8n8.x4.shared.b16 {%0,%1,%2,%3}, [%4];"
                 : "=r"(r[0]), "=r"(r[1]), "=r"(r[2]), "=r"(r[3]) : "r"(addr));
}

__device__ __forceinline__ void mma16816(float* d, const uint32_t* a, uint32_t b0, uint32_t b1) {
    asm volatile("mma.sync.aligned.m16n8k16.row.col.f32.bf16.bf16.f32 "
                 "{%0,%1,%2,%3}, {%4,%5,%6,%7}, {%8,%9}, {%0,%1,%2,%3};"
                 : "+f"(d[0]), "+f"(d[1]), "+f"(d[2]), "+f"(d[3])
                 : "r"(a[0]), "r"(a[1]), "r"(a[2]), "r"(a[3]), "r"(b0), "r"(b1));
}

__device__ __forceinline__ void mma16816h(float* d, const uint32_t* a, uint32_t b0, uint32_t b1) {
    asm volatile("mma.sync.aligned.m16n8k16.row.col.f32.f16.f16.f32 "
                 "{%0,%1,%2,%3}, {%4,%5,%6,%7}, {%8,%9}, {%0,%1,%2,%3};"
                 : "+f"(d[0]), "+f"(d[1]), "+f"(d[2]), "+f"(d[3])
                 : "r"(a[0]), "r"(a[1]), "r"(a[2]), "r"(a[3]), "r"(b0), "r"(b1));
}

__device__ __forceinline__ void bulk_g2s(uint32_t dst, const void* src, uint32_t bytes, uint32_t mbar) {
    asm volatile("cp.async.bulk.shared::cluster.global.mbarrier::complete_tx::bytes "
                 "[%0], [%1], %2, [%3];"
                 :: "r"(dst), "l"(src), "r"(bytes), "r"(mbar) : "memory");
}

#define MBAR_INIT(addr, cnt) \
    asm volatile("mbarrier.init.shared.b64 [%0], %1;" :: "r"(addr), "r"(cnt) : "memory")
#define MBAR_EXPECT_TX(addr, tx) \
    asm volatile("mbarrier.arrive.expect_tx.shared::cta.b64 _, [%0], %1;" :: "r"(addr), "r"(tx) : "memory")
#define FENCE_ASYNC_SHARED() asm volatile("fence.proxy.async.shared::cta;" ::: "memory")

#define MBAR_WAIT_PARITY(addr, par) do {                                             \
    uint32_t _mbar = (uint32_t)(addr);                                               \
    uint32_t _par  = (uint32_t)(par);                                                \
    uint32_t _done;                                                                  \
    asm volatile("{\n\t.reg .pred p;\n\t"                                            \
        "mbarrier.try_wait.parity.acquire.cta.shared::cta.b64 p, [%1], %2;\n\t"      \
        "selp.b32 %0, 1, 0, p;\n\t}"                                                 \
        : "=r"(_done) : "r"(_mbar), "r"(_par) : "memory");                           \
    if (!_done) {                                                                    \
        asm volatile("{\n\t.reg .pred P1;\n\t"                                       \
            "WAIT_LOOP_%=:\n\t"                                                      \
            "mbarrier.try_wait.parity.acquire.cta.shared::cta.b64 P1, [%0], %1, 0x989680;\n\t" \
            "@P1 bra.uni WAIT_DONE_%=;\n\t"                                          \
            "bra.uni WAIT_LOOP_%=;\n\t"                                              \
            "WAIT_DONE_%=:\n\t}"                                                     \
            :: "r"(_mbar), "r"(_par) : "memory");                                    \
    }                                                                                \
} while (0)

__device__ __forceinline__ void split1(float v, bf16& h, bf16& l) {
    h = __float2bfloat16_rn(v);
    l = __float2bfloat16_rn(v - __bfloat162float(h));
}

__device__ __host__ __forceinline__ uint32_t chunk_off(int r, int cc) {
    return (uint32_t)((r & 7) * 16 + (cc + 4 * (r >> 3)) * 128);
}

// ---------------------------------------------------------------------------
// 3-product bf16 GEMM (FROZEN inner loop; R11: ~97% of legacy-HMMA ceiling)
// CTA 128x256, 16 warps (4m x 4n) of 32x64, BK=32, 4-stage bulk-copy ring.
// Stage: [Ah 8K][Al 8K][Bh 16K][Bl 16K] = 48KB.
// ---------------------------------------------------------------------------
#define STAGE_BYTES 49152
#define NSTAGE 4
#define SMEM_BYTES (1024 + NSTAGE * STAGE_BYTES)   // 197632
#define NTHREADS 512

// MODE 0: A-role bf16 split +bias | 1: B-role bf16 split +bias
// MODE 2: fp32 row store          | 3: V^T fp16-h transposed +bias
template <int MODE, int NCT, int C0>
__device__ __forceinline__ void gemm_core(
    const char* __restrict__ Ap, const char* __restrict__ Bp,
    int K, const float* __restrict__ bias,
    char* __restrict__ outp, float* __restrict__ outf,
    int ldc, int m0, int n0, int cm0)
{
    extern __shared__ char smem[];
    const uint32_t sb = smem_u32(smem);
    const int tid = threadIdx.x, lane = tid & 31, wid = tid >> 5;
    const int wm = wid & 3, wn = wid >> 2;

    float acc[2][8][4];
#pragma unroll
    for (int i = 0; i < 2; i++)
#pragma unroll
        for (int j = 0; j < 8; j++)
#pragma unroll
            for (int e = 0; e < 4; e++) acc[i][j][e] = 0.f;

    const int NC = K >> 5;
    const size_t a_base = (size_t)(m0 >> 7) * NCT + C0;
    const size_t b_base = (size_t)(n0 >> 8) * NCT + C0;

    if (tid == 0) {
#pragma unroll
        for (int s = 0; s < NSTAGE; s++) MBAR_INIT(sb + s * 8, 1);
    }
    __syncthreads();
    FENCE_ASYNC_SHARED();

    auto issue = [&](int s) {
        const uint32_t mb  = sb + (uint32_t)(s & 3) * 8;
        const uint32_t dst = sb + 1024 + (uint32_t)(s & 3) * STAGE_BYTES;
        MBAR_EXPECT_TX(mb, (uint32_t)STAGE_BYTES);
        bulk_g2s(dst,           Ap + (a_base + s) * PANEL_A, PANEL_A, mb);
        bulk_g2s(dst + PANEL_A, Bp + (b_base + s) * PANEL_B, PANEL_B, mb);
    };

    if (tid == 0) { issue(0); issue(1); issue(2); }

    const uint32_t lsel = (lane & 7) * 16 + (lane >> 4) * 128 + ((lane >> 3) & 1) * 512;

#pragma unroll 1
    for (int c = 0; c < NC; c++) {
        MBAR_WAIT_PARITY(sb + (c & 3) * 8, (c >> 2) & 1);
        __syncthreads();
        if (tid == 0 && c + 3 < NC) issue(c + 3);

        const uint32_t base = sb + 1024 + (uint32_t)(c & 3) * STAGE_BYTES;

#pragma unroll
        for (int ks = 0; ks < 2; ks++) {
            const uint32_t koff = (uint32_t)ks * 256;
            uint32_t ah[2][4], al[2][4];
#pragma unroll
            for (int mi = 0; mi < 2; mi++) {
                uint32_t g = (uint32_t)(wm * 4 + mi * 2);
                uint32_t off = base + lsel + koff + g * 512;
                ldsm4(ah[mi], off);
                ldsm4(al[mi], off + 8192);
            }
#pragma unroll
            for (int bi = 0; bi < 4; bi++) {
                uint32_t g = (uint32_t)(wn * 8 + bi * 2);
                uint32_t off = base + 16384 + lsel + koff + g * 512;
                uint32_t bh[4], bl[4];
                ldsm4(bh, off);
                ldsm4(bl, off + 16384);
#pragma unroll
                for (int mi = 0; mi < 2; mi++)
#pragma unroll
                    for (int j = 0; j < 2; j++) {
                        const int ni = bi * 2 + j;
                        mma16816(acc[mi][ni], ah[mi], bh[j], bh[j + 2]);
                        mma16816(acc[mi][ni], ah[mi], bl[j], bl[j + 2]);
                        mma16816(acc[mi][ni], al[mi], bh[j], bh[j + 2]);
                    }
            }
        }
    }

    const int rl = lane >> 2, cl = (lane & 3) * 2;
#pragma unroll
    for (int mi = 0; mi < 2; mi++)
#pragma unroll
        for (int ni = 0; ni < 8; ni++) {
            const int col = n0 + wn * 64 + ni * 8 + cl;
#pragma unroll
            for (int rh = 0; rh < 2; rh++) {
                float v0 = acc[mi][ni][rh * 2 + 0];
                float v1 = acc[mi][ni][rh * 2 + 1];
                if (MODE != 2) {
                    v0 += __ldg(bias + col);
                    v1 += __ldg(bias + col + 1);
                }
                const int row = m0 + wm * 32 + mi * 16 + rl + rh * 8;
                if (MODE == 2) {
                    float2 o = {v0, v1};
                    *(float2*)(outf + (size_t)row * ldc + col) = o;
                } else if (MODE == 0) {
                    bf16 h0, l0, h1, l1;
                    split1(v0, h0, l0); split1(v1, h1, l1);
                    uint32_t hp = ((uint32_t)__bfloat16_as_ushort(h1) << 16) | __bfloat16_as_ushort(h0);
                    uint32_t lp = ((uint32_t)__bfloat16_as_ushort(l1) << 16) | __bfloat16_as_ushort(l0);
                    size_t off = ((size_t)(row >> 7) * (ldc >> 5) + (col >> 5)) * PANEL_A
                               + chunk_off(row & 127, (col & 31) >> 3) + (col & 7) * 2;
                    *(uint32_t*)(outp + off)        = hp;
                    *(uint32_t*)(outp + off + 8192) = lp;
                } else if (MODE == 1) {
                    bf16 h0, l0, h1, l1;
                    split1(v0, h0, l0); split1(v1, h1, l1);
                    uint32_t hp = ((uint32_t)__bfloat16_as_ushort(h1) << 16) | __bfloat16_as_ushort(h0);
                    uint32_t lp = ((uint32_t)__bfloat16_as_ushort(l1) << 16) | __bfloat16_as_ushort(l0);
                    size_t off = ((size_t)(row >> 8) * (ldc >> 5) + (col >> 5)) * PANEL_B
                               + chunk_off(row & 255, (col & 31) >> 3) + (col & 7) * 2;
                    *(uint32_t*)(outp + off)         = hp;
                    *(uint32_t*)(outp + off + 16384) = lp;
                } else {   // MODE 3: V^T fp16-h transposed panels (B-role h-only)
                    const int mloc = cm0 + wm * 32 + mi * 16 + rl + rh * 8;
                    __half h0 = __float2half_rn(v0);
                    __half h1 = __float2half_rn(v1);
                    size_t pb = ((size_t)(col >> 8) * (SEQ >> 5) + (mloc >> 5)) * PANEL_BH;
                    uint32_t co0 = chunk_off(col & 255, (mloc & 31) >> 3) + (mloc & 7) * 2;
                    uint32_t co1 = chunk_off((col + 1) & 255, (mloc & 31) >> 3) + (mloc & 7) * 2;
                    *(__half*)(outp + pb + co0) = h0;
                    *(__half*)(outp + pb + co1) = h1;
                }
            }
        }
}

// ---------------------------------------------------------------------------
// 1-product fp16 GEMM (context): C = P(fp16 h) * V^T(fp16 h), fp32 acc/out.
// Stage: [Ah 8K][Bh 16K] = 24KB; 4-stage ring; same warp layout.
// ---------------------------------------------------------------------------
#define STAGE1_BYTES 24576
#define SMEM1_BYTES (1024 + NSTAGE * STAGE1_BYTES)   // 99328

__global__ void __launch_bounds__(NTHREADS, 1) context1_tc(float* __restrict__ ctx)
{
    extern __shared__ char smem[];
    const uint32_t sb = smem_u32(smem);
    const int tid = threadIdx.x, lane = tid & 31, wid = tid >> 5;
    const int wm = wid & 3, wn = wid >> 2;
    const int b = blockIdx.z;
    const int m0 = blockIdx.y * 128, n0 = blockIdx.x * 256;

    const char* Ap = g_pph  + (size_t)b * 16 * 64 * PANEL_AH;
    const char* Bp = g_vthp + (size_t)b * 4  * 64 * PANEL_BH;
    float* outf = ctx + (size_t)b * SEQ * HDIM;

    float acc[2][8][4];
#pragma unroll
    for (int i = 0; i < 2; i++)
#pragma unroll
        for (int j = 0; j < 8; j++)
#pragma unroll
            for (int e = 0; e < 4; e++) acc[i][j][e] = 0.f;

    const size_t a_base = (size_t)(m0 >> 7) * 64;
    const size_t b_base = (size_t)(n0 >> 8) * 64;

    if (tid == 0) {
#pragma unroll
        for (int s = 0; s < NSTAGE; s++) MBAR_INIT(sb + s * 8, 1);
    }
    __syncthreads();
    FENCE_ASYNC_SHARED();

    auto issue = [&](int s) {
        const uint32_t mb  = sb + (uint32_t)(s & 3) * 8;
        const uint32_t dst = sb + 1024 + (uint32_t)(s & 3) * STAGE1_BYTES;
        MBAR_EXPECT_TX(mb, (uint32_t)STAGE1_BYTES);
        bulk_g2s(dst,            Ap + (a_base + s) * PANEL_AH, PANEL_AH, mb);
        bulk_g2s(dst + PANEL_AH, Bp + (b_base + s) * PANEL_BH, PANEL_BH, mb);
    };

    if (tid == 0) { issue(0); issue(1); issue(2); }

    const uint32_t lsel = (lane & 7) * 16 + (lane >> 4) * 128 + ((lane >> 3) & 1) * 512;

#pragma unroll 1
    for (int c = 0; c < 64; c++) {
        MBAR_WAIT_PARITY(sb + (c & 3) * 8, (c >> 2) & 1);
        __syncthreads();
        if (tid == 0 && c + 3 < 64) issue(c + 3);

        const uint32_t base = sb + 1024 + (uint32_t)(c & 3) * STAGE1_BYTES;

#pragma unroll
        for (int ks = 0; ks < 2; ks++) {
            const uint32_t koff = (uint32_t)ks * 256;
            uint32_t ah[2][4];
#pragma unroll
            for (int mi = 0; mi < 2; mi++) {
                uint32_t g = (uint32_t)(wm * 4 + mi * 2);
                ldsm4(ah[mi], base + lsel + koff + g * 512);
            }
#pragma unroll
            for (int bi = 0; bi < 4; bi++) {
                uint32_t g = (uint32_t)(wn * 8 + bi * 2);
                uint32_t bh[4];
                ldsm4(bh, base + 8192 + lsel + koff + g * 512);
#pragma unroll
                for (int mi = 0; mi < 2; mi++)
#pragma unroll
                    for (int j = 0; j < 2; j++)
                        mma16816h(acc[mi][bi * 2 + j], ah[mi], bh[j], bh[j + 2]);
            }
        }
    }

    const int rl = lane >> 2, cl = (lane & 3) * 2;
#pragma unroll
    for (int mi = 0; mi < 2; mi++)
#pragma unroll
        for (int ni = 0; ni < 8; ni++) {
            const int col = n0 + wn * 64 + ni * 8 + cl;
#pragma unroll
            for (int rh = 0; rh < 2; rh++) {
                const int row = m0 + wm * 32 + mi * 16 + rl + rh * 8;
                float2 o = {acc[mi][ni][rh * 2 + 0], acc[mi][ni][rh * 2 + 1]};
                *(float2*)(outf + (size_t)row * HDIM + col) = o;
            }
        }
}

// ---------------------------------------------------------------------------
// Fused split: one launch packs x (A-role) + Wq/Wk/Wv (B-role)
// ---------------------------------------------------------------------------
__global__ void __launch_bounds__(256) split_fused(
    const float* __restrict__ x, const float* __restrict__ Wq,
    const float* __restrict__ Wk, const float* __restrict__ Wv,
    char* __restrict__ xp, char* __restrict__ wqp,
    char* __restrict__ wkp, char* __restrict__ wvp)
{
    const int bid = blockIdx.x;
    const float* src;
    char* dst;
    int i;
    bool arole;
    if (bid < 8192) {
        src = x; dst = xp; i = bid * 256 + threadIdx.x; arole = true;
    } else {
        const int w = (bid - 8192) >> 10;
        const int b2 = (bid - 8192) & 1023;
        src = (w == 0) ? Wq : (w == 1) ? Wk : Wv;
        dst = (w == 0) ? wqp : (w == 1) ? wkp : wvp;
        i = b2 * 256 + threadIdx.x; arole = false;
    }
    const int idx = i * 4;
    const int row = idx >> 10, k = idx & 1023;
    float4 v = *(const float4*)(src + idx);
    float f[4] = {v.x, v.y, v.z, v.w};
    uint32_t hp[2], lp[2];
#pragma unroll
    for (int j = 0; j < 2; j++) {
        bf16 h0, l0, h1, l1;
        split1(f[2 * j], h0, l0); split1(f[2 * j + 1], h1, l1);
        hp[j] = ((uint32_t)__bfloat16_as_ushort(h1) << 16) | __bfloat16_as_ushort(h0);
        lp[j] = ((uint32_t)__bfloat16_as_ushort(l1) << 16) | __bfloat16_as_ushort(l0);
    }
    if (arole) {
        size_t off = ((size_t)(row >> 7) * 32 + (k >> 5)) * PANEL_A
                   + chunk_off(row & 127, (k & 31) >> 3) + (k & 7) * 2;
        *(uint2*)(dst + off)        = make_uint2(hp[0], hp[1]);
        *(uint2*)(dst + off + 8192) = make_uint2(lp[0], lp[1]);
    } else {
        size_t off = ((size_t)(row >> 8) * 32 + (k >> 5)) * PANEL_B
                   + chunk_off(row & 255, (k & 31) >> 3) + (k & 7) * 2;
        *(uint2*)(dst + off)         = make_uint2(hp[0], hp[1]);
        *(uint2*)(dst + off + 16384) = make_uint2(lp[0], lp[1]);
    }
}

// ---------------------------------------------------------------------------
// GEMM kernels
// ---------------------------------------------------------------------------
__global__ void __launch_bounds__(NTHREADS, 1) qkv_qk_tc(
    const float* __restrict__ bq, const float* __restrict__ bk)
{
    const int m0 = blockIdx.y * 128;
    const int n0 = blockIdx.x * 256;
    if (blockIdx.z == 0) {
        gemm_core<0, 32, 0>(g_xp, g_wqp, HDIM, bq, g_qp, nullptr, HDIM, m0, n0, 0);
    } else {
        gemm_core<1, 32, 0>(g_xp, g_wkp, HDIM, bk, g_kp, nullptr, HDIM, m0, n0, 0);
    }
}

__global__ void __launch_bounds__(NTHREADS, 1) vt_tc(const float* __restrict__ bv)
{
    const int m0 = blockIdx.y * 128;
    const int n0 = blockIdx.x * 256;
    const int b = m0 >> 11;
    gemm_core<3, 32, 0>(g_xp, g_wvp, HDIM, bv,
                        g_vthp + (size_t)b * 4 * 64 * PANEL_BH, nullptr, SEQ,
                        m0, n0, m0 & (SEQ - 1));
}

__global__ void __launch_bounds__(NTHREADS, 1) scores_tc()
{
    const int z = blockIdx.z;
    const int b = z & (BATCH - 1), half = z >> 2;
    const char* qp = g_qp + (size_t)b * 16 * 32 * PANEL_A;
    const char* kp = g_kp + (size_t)b * 8 * 32 * PANEL_B;
    const int m0 = blockIdx.y * 128, n0 = blockIdx.x * 256;
    if (half == 0) {
        gemm_core<2, 32, 0>(qp, kp, HDIM / 2, nullptr, nullptr,
                            g_p + (size_t)b * SEQ * SEQ, SEQ, m0, n0, 0);
    } else {
        gemm_core<2, 32, 16>(qp, kp, HDIM / 2, nullptr, nullptr,
                             g_p2 + (size_t)b * SEQ * SEQ, SEQ, m0, n0, 0);
    }
}

// ---------------------------------------------------------------------------
// Softmax: sum split-K partials, softmax, store probs as fp16-h panels
// ---------------------------------------------------------------------------
__global__ void __launch_bounds__(256) softmax_kernel()
{
    const int row = blockIdx.x;
    const float4* p4 = (const float4*)(g_p  + (size_t)row * SEQ) + threadIdx.x * 2;
    const float4* q4 = (const float4*)(g_p2 + (size_t)row * SEQ) + threadIdx.x * 2;
    const int tid = threadIdx.x;

    float4 va = p4[0], vb = p4[1];
    float4 wa = q4[0], wb = q4[1];
    float v[8] = {va.x + wa.x, va.y + wa.y, va.z + wa.z, va.w + wa.w,
                  vb.x + wb.x, vb.y + wb.y, vb.z + wb.z, vb.w + wb.w};
    float m = v[0];
#pragma unroll
    for (int i = 1; i < 8; i++) m = fmaxf(m, v[i]);

    __shared__ float red[8];
#pragma unroll
    for (int o = 16; o; o >>= 1) m = fmaxf(m, __shfl_xor_sync(0xffffffffu, m, o));
    if ((tid & 31) == 0) red[tid >> 5] = m;
    __syncthreads();
    m = red[0];
#pragma unroll
    for (int i = 1; i < 8; i++) m = fmaxf(m, red[i]);
    __syncthreads();

    float s = 0.f;
#pragma unroll
    for (int i = 0; i < 8; i++) {
        v[i] = __expf(v[i] - m);
        s += v[i];
    }
#pragma unroll
    for (int o = 16; o; o >>= 1) s += __shfl_xor_sync(0xffffffffu, s, o);
    if ((tid & 31) == 0) red[tid >> 5] = s;
    __syncthreads();
    float tot = 0.f;
#pragma unroll
    for (int i = 0; i < 8; i++) tot += red[i];
    const float inv = 1.0f / tot;

    uint32_t hp[4];
#pragma unroll
    for (int j = 0; j < 4; j++) {
        __half h0 = __float2half_rn(v[2 * j] * inv);
        __half h1 = __float2half_rn(v[2 * j + 1] * inv);
        hp[j] = ((uint32_t)__half_as_ushort(h1) << 16) | __half_as_ushort(h0);
    }
    const int col0 = tid * 8;
    const size_t off = ((size_t)(row >> 7) * 64 + (col0 >> 5)) * PANEL_AH
                     + chunk_off(row & 127, (col0 & 31) >> 3);
    *(uint4*)(g_pph + off) = make_uint4(hp[0], hp[1], hp[2], hp[3]);
}

// ---------------------------------------------------------------------------
// Column sums of probs (fp16-h panels), per-panel reduction
// ---------------------------------------------------------------------------
__global__ void __launch_bounds__(256) colsum_kernel(float* __restrict__ out)
{
    const int pk = blockIdx.x;   // 0..63 k-panel
    const int pr = blockIdx.y;   // 0..63 row-panel
    const char* panel = g_pph + ((size_t)pr * 64 + pk) * PANEL_AH;
    const int tid = threadIdx.x;
    const int col = tid & 31;
    const int rg  = tid >> 5;

    const uint32_t cbase = ((col & 31) >> 3) * 128 + (col & 7) * 2;
    float s = 0.f;
#pragma unroll
    for (int r = rg * 16; r < rg * 16 + 16; r++) {
        uint32_t off = (uint32_t)((r & 7) * 16 + 4 * (r >> 3) * 128) + cbase;
        s += __half2float(*(const __half*)(panel + off));
    }
    __shared__ float part[256];
    part[tid] = s;
    __syncthreads();
    if (tid < 32) {
        float t = 0.f;
#pragma unroll
        for (int j = 0; j < 8; j++) t += part[tid + 32 * j];
        const int batch = pr >> 4;
        atomicAdd(out + batch * SEQ + pk * 32 + tid, t);
    }
}

// ---------------------------------------------------------------------------
extern "C" void kernel_launch(void* const* d_in, const int* in_sizes, int n_in,
                              void* d_out, int out_size)
{
    const float* x  = (const float*)d_in[0];
    const float* Wq = (const float*)d_in[1];
    const float* bq = (const float*)d_in[2];
    const float* Wk = (const float*)d_in[3];
    const float* bk = (const float*)d_in[4];
    const float* Wv = (const float*)d_in[5];
    const float* bv = (const float*)d_in[6];

    float* ctx = (float*)d_out;
    float* sc  = ctx + (size_t)BATCH * SEQ * HDIM;

    cudaFuncSetAttribute((const void*)qkv_qk_tc,
                         cudaFuncAttributeMaxDynamicSharedMemorySize, SMEM_BYTES);
    cudaFuncSetAttribute((const void*)vt_tc,
                         cudaFuncAttributeMaxDynamicSharedMemorySize, SMEM_BYTES);
    cudaFuncSetAttribute((const void*)scores_tc,
                         cudaFuncAttributeMaxDynamicSharedMemorySize, SMEM_BYTES);
    cudaFuncSetAttribute((const void*)context1_tc,
                         cudaFuncAttributeMaxDynamicSharedMemorySize, SMEM1_BYTES);

    char *xp, *wqp, *wkp, *wvp;
    cudaGetSymbolAddress((void**)&xp,  g_xp);
    cudaGetSymbolAddress((void**)&wqp, g_wqp);
    cudaGetSymbolAddress((void**)&wkp, g_wkp);
    cudaGetSymbolAddress((void**)&wvp, g_wvp);

    static cudaStream_t s2 = nullptr;
    static cudaEvent_t evFork = nullptr, evJoin = nullptr;
    if (s2 == nullptr) {
        cudaStreamCreateWithFlags(&s2, cudaStreamNonBlocking);
        cudaEventCreateWithFlags(&evFork, cudaEventDisableTiming);
        cudaEventCreateWithFlags(&evJoin, cudaEventDisableTiming);
    }

    cudaMemsetAsync(sc, 0, (size_t)BATCH * SEQ * sizeof(float));

    split_fused<<<8192 + 3 * 1024, 256>>>(x, Wq, Wk, Wv, xp, wqp, wkp, wvp);

    // Fork: V^T projection on stream 2 (depends only on split_fused)
    cudaEventRecord(evFork, 0);
    cudaStreamWaitEvent(s2, evFork, 0);
    vt_tc<<<dim3(HDIM / 256, MTOT / 128), NTHREADS, SMEM_BYTES, s2>>>(bv);
    cudaEventRecord(evJoin, s2);

    // Main stream: Q/K projections -> scores -> softmax -> colsum
    qkv_qk_tc<<<dim3(HDIM / 256, MTOT / 128, 2), NTHREADS, SMEM_BYTES>>>(bq, bk);
    scores_tc<<<dim3(SEQ / 256, SEQ / 128, BATCH * 2), NTHREADS, SMEM_BYTES>>>();
    softmax_kernel<<<MTOT, 256>>>();
    colsum_kernel<<<dim3(64, 64), 256>>>(sc);

    // Join: context needs V^T
    cudaStreamWaitEvent(0, evJoin, 0);
    context1_tc<<<dim3(HDIM / 256, SEQ / 128, BATCH), NTHREADS, SMEM1_BYTES>>>(ctx);
}

// round 16
// speedup vs baseline: 1.3549x; 1.0907x over previous
#include <cuda_runtime.h>
#include <cuda_bf16.h>
#include <cuda_fp16.h>
#include <stdint.h>

#define HDIM 1024
#define SEQ  2048
#define BATCH 4
#define MTOT (BATCH * SEQ)

typedef __nv_bfloat16 bf16;

// ---------------------------------------------------------------------------
// Panel geometry
// A-role panels: 128 rows x 32 k, [h 8KB | l 8KB] = 16KB (bf16 split)
// B-role panels: 256 rows x 32 k, [h 16KB | l 16KB] = 32KB (bf16 split)
// fp16 h-only: A-role 8KB, B-role 16KB (same chunk layout, hi half only)
// Within each half: 16B chunk (r, cc) at (r&7)*16 + (cc + 4*(r>>3))*128
// ---------------------------------------------------------------------------
#define PANEL_A 16384
#define PANEL_B 32768
#define PANEL_AH 8192
#define PANEL_BH 16384

// Scratch (__device__ globals: allocation-free rule)
__device__ __align__(128) char g_xp [(size_t)64 * 32 * PANEL_A];            // x   A-role bf16
__device__ __align__(128) char g_wqp[(size_t)4  * 32 * PANEL_B];            // Wq  B-role bf16
__device__ __align__(128) char g_wkp[(size_t)4  * 32 * PANEL_B];
__device__ __align__(128) char g_wvp[(size_t)4  * 32 * PANEL_B];
__device__ __align__(128) char g_qp [(size_t)64 * 32 * PANEL_A];            // Q   A-role bf16
__device__ __align__(128) char g_kp [(size_t)32 * 32 * PANEL_B];            // K   B-role bf16
__device__ __align__(128) char g_vthp[(size_t)BATCH * 4 * 64 * PANEL_BH];   // V^T B-role fp16 h
__device__ float g_p [(size_t)BATCH * SEQ * SEQ];                           // logits partial 0
__device__ float g_p2[(size_t)BATCH * SEQ * SEQ];                           // logits partial 1
__device__ __align__(128) char g_pph[(size_t)64 * 64 * PANEL_AH];           // probs A-role fp16 h

// ---------------------------------------------------------------------------
// Helpers
// ---------------------------------------------------------------------------
__device__ __forceinline__ uint32_t smem_u32(const void* p) {
    uint32_t a;
    asm("{ .reg .u64 t; cvta.to.shared.u64 t, %1; cvt.u32.u64 %0, t; }" : "=r"(a) : "l"(p));
    return a;
}

__device__ __forceinline__ void ldsm4(uint32_t* r, uint32_t addr) {
    asm volatile("ldmatrix.sync.aligned.m8n8.x4.shared.b16 {%0,%1,%2,%3}, [%4];"
                 : "=r"(r[0]), "=r"(r[1]), "=r"(r[2]), "=r"(r[3]) : "r"(addr));
}

__device__ __forceinline__ void mma16816(float* d, const uint32_t* a, uint32_t b0, uint32_t b1) {
    asm volatile("mma.sync.aligned.m16n8k16.row.col.f32.bf16.bf16.f32 "
                 "{%0,%1,%2,%3}, {%4,%5,%6,%7}, {%8,%9}, {%0,%1,%2,%3};"
                 : "+f"(d[0]), "+f"(d[1]), "+f"(d[2]), "+f"(d[3])
                 : "r"(a[0]), "r"(a[1]), "r"(a[2]), "r"(a[3]), "r"(b0), "r"(b1));
}

__device__ __forceinline__ void mma16816h(float* d, const uint32_t* a, uint32_t b0, uint32_t b1) {
    asm volatile("mma.sync.aligned.m16n8k16.row.col.f32.f16.f16.f32 "
                 "{%0,%1,%2,%3}, {%4,%5,%6,%7}, {%8,%9}, {%0,%1,%2,%3};"
                 : "+f"(d[0]), "+f"(d[1]), "+f"(d[2]), "+f"(d[3])
                 : "r"(a[0]), "r"(a[1]), "r"(a[2]), "r"(a[3]), "r"(b0), "r"(b1));
}

__device__ __forceinline__ void bulk_g2s(uint32_t dst, const void* src, uint32_t bytes, uint32_t mbar) {
    asm volatile("cp.async.bulk.shared::cluster.global.mbarrier::complete_tx::bytes "
                 "[%0], [%1], %2, [%3];"
                 :: "r"(dst), "l"(src), "r"(bytes), "r"(mbar) : "memory");
}

#define MBAR_INIT(addr, cnt) \
    asm volatile("mbarrier.init.shared.b64 [%0], %1;" :: "r"(addr), "r"(cnt) : "memory")
#define MBAR_EXPECT_TX(addr, tx) \
    asm volatile("mbarrier.arrive.expect_tx.shared::cta.b64 _, [%0], %1;" :: "r"(addr), "r"(tx) : "memory")
#define FENCE_ASYNC_SHARED() asm volatile("fence.proxy.async.shared::cta;" ::: "memory")

#define MBAR_WAIT_PARITY(addr, par) do {                                             \
    uint32_t _mbar = (uint32_t)(addr);                                               \
    uint32_t _par  = (uint32_t)(par);                                                \
    uint32_t _done;                                                                  \
    asm volatile("{\n\t.reg .pred p;\n\t"                                            \
        "mbarrier.try_wait.parity.acquire.cta.shared::cta.b64 p, [%1], %2;\n\t"      \
        "selp.b32 %0, 1, 0, p;\n\t}"                                                 \
        : "=r"(_done) : "r"(_mbar), "r"(_par) : "memory");                           \
    if (!_done) {                                                                    \
        asm volatile("{\n\t.reg .pred P1;\n\t"                                       \
            "WAIT_LOOP_%=:\n\t"                                                      \
            "mbarrier.try_wait.parity.acquire.cta.shared::cta.b64 P1, [%0], %1, 0x989680;\n\t" \
            "@P1 bra.uni WAIT_DONE_%=;\n\t"                                          \
            "bra.uni WAIT_LOOP_%=;\n\t"                                              \
            "WAIT_DONE_%=:\n\t}"                                                     \
            :: "r"(_mbar), "r"(_par) : "memory");                                    \
    }                                                                                \
} while (0)

__device__ __forceinline__ void split1(float v, bf16& h, bf16& l) {
    h = __float2bfloat16_rn(v);
    l = __float2bfloat16_rn(v - __bfloat162float(h));
}

__device__ __host__ __forceinline__ uint32_t chunk_off(int r, int cc) {
    return (uint32_t)((r & 7) * 16 + (cc + 4 * (r >> 3)) * 128);
}

// ---------------------------------------------------------------------------
// 3-product bf16 GEMM (FROZEN inner loop; R11: ~97% of legacy-HMMA ceiling)
// CTA 128x256, 16 warps (4m x 4n) of 32x64, BK=32, 4-stage bulk-copy ring.
// Stage: [Ah 8K][Al 8K][Bh 16K][Bl 16K] = 48KB.
// ---------------------------------------------------------------------------
#define STAGE_BYTES 49152
#define NSTAGE 4
#define SMEM_BYTES (1024 + NSTAGE * STAGE_BYTES)   // 197632
#define NTHREADS 512

// MODE 0: A-role bf16 split +bias | 1: B-role bf16 split +bias
// MODE 2: fp32 row store          | 3: V^T fp16-h transposed +bias
template <int MODE, int NCT, int C0>
__device__ __forceinline__ void gemm_core(
    const char* __restrict__ Ap, const char* __restrict__ Bp,
    int K, const float* __restrict__ bias,
    char* __restrict__ outp, float* __restrict__ outf,
    int ldc, int m0, int n0, int cm0)
{
    extern __shared__ char smem[];
    const uint32_t sb = smem_u32(smem);
    const int tid = threadIdx.x, lane = tid & 31, wid = tid >> 5;
    const int wm = wid & 3, wn = wid >> 2;

    float acc[2][8][4];
#pragma unroll
    for (int i = 0; i < 2; i++)
#pragma unroll
        for (int j = 0; j < 8; j++)
#pragma unroll
            for (int e = 0; e < 4; e++) acc[i][j][e] = 0.f;

    const int NC = K >> 5;
    const size_t a_base = (size_t)(m0 >> 7) * NCT + C0;
    const size_t b_base = (size_t)(n0 >> 8) * NCT + C0;

    if (tid == 0) {
#pragma unroll
        for (int s = 0; s < NSTAGE; s++) MBAR_INIT(sb + s * 8, 1);
    }
    __syncthreads();
    FENCE_ASYNC_SHARED();

    auto issue = [&](int s) {
        const uint32_t mb  = sb + (uint32_t)(s & 3) * 8;
        const uint32_t dst = sb + 1024 + (uint32_t)(s & 3) * STAGE_BYTES;
        MBAR_EXPECT_TX(mb, (uint32_t)STAGE_BYTES);
        bulk_g2s(dst,           Ap + (a_base + s) * PANEL_A, PANEL_A, mb);
        bulk_g2s(dst + PANEL_A, Bp + (b_base + s) * PANEL_B, PANEL_B, mb);
    };

    if (tid == 0) { issue(0); issue(1); issue(2); }

    const uint32_t lsel = (lane & 7) * 16 + (lane >> 4) * 128 + ((lane >> 3) & 1) * 512;

#pragma unroll 1
    for (int c = 0; c < NC; c++) {
        MBAR_WAIT_PARITY(sb + (c & 3) * 8, (c >> 2) & 1);
        __syncthreads();
        if (tid == 0 && c + 3 < NC) issue(c + 3);

        const uint32_t base = sb + 1024 + (uint32_t)(c & 3) * STAGE_BYTES;

#pragma unroll
        for (int ks = 0; ks < 2; ks++) {
            const uint32_t koff = (uint32_t)ks * 256;
            uint32_t ah[2][4], al[2][4];
#pragma unroll
            for (int mi = 0; mi < 2; mi++) {
                uint32_t g = (uint32_t)(wm * 4 + mi * 2);
                uint32_t off = base + lsel + koff + g * 512;
                ldsm4(ah[mi], off);
                ldsm4(al[mi], off + 8192);
            }
#pragma unroll
            for (int bi = 0; bi < 4; bi++) {
                uint32_t g = (uint32_t)(wn * 8 + bi * 2);
                uint32_t off = base + 16384 + lsel + koff + g * 512;
                uint32_t bh[4], bl[4];
                ldsm4(bh, off);
                ldsm4(bl, off + 16384);
#pragma unroll
                for (int mi = 0; mi < 2; mi++)
#pragma unroll
                    for (int j = 0; j < 2; j++) {
                        const int ni = bi * 2 + j;
                        mma16816(acc[mi][ni], ah[mi], bh[j], bh[j + 2]);
                        mma16816(acc[mi][ni], ah[mi], bl[j], bl[j + 2]);
                        mma16816(acc[mi][ni], al[mi], bh[j], bh[j + 2]);
                    }
            }
        }
    }

    const int rl = lane >> 2, cl = (lane & 3) * 2;
#pragma unroll
    for (int mi = 0; mi < 2; mi++)
#pragma unroll
        for (int ni = 0; ni < 8; ni++) {
            const int col = n0 + wn * 64 + ni * 8 + cl;
#pragma unroll
            for (int rh = 0; rh < 2; rh++) {
                float v0 = acc[mi][ni][rh * 2 + 0];
                float v1 = acc[mi][ni][rh * 2 + 1];
                if (MODE != 2) {
                    v0 += __ldg(bias + col);
                    v1 += __ldg(bias + col + 1);
                }
                const int row = m0 + wm * 32 + mi * 16 + rl + rh * 8;
                if (MODE == 2) {
                    float2 o = {v0, v1};
                    *(float2*)(outf + (size_t)row * ldc + col) = o;
                } else if (MODE == 0) {
                    bf16 h0, l0, h1, l1;
                    split1(v0, h0, l0); split1(v1, h1, l1);
                    uint32_t hp = ((uint32_t)__bfloat16_as_ushort(h1) << 16) | __bfloat16_as_ushort(h0);
                    uint32_t lp = ((uint32_t)__bfloat16_as_ushort(l1) << 16) | __bfloat16_as_ushort(l0);
                    size_t off = ((size_t)(row >> 7) * (ldc >> 5) + (col >> 5)) * PANEL_A
                               + chunk_off(row & 127, (col & 31) >> 3) + (col & 7) * 2;
                    *(uint32_t*)(outp + off)        = hp;
                    *(uint32_t*)(outp + off + 8192) = lp;
                } else if (MODE == 1) {
                    bf16 h0, l0, h1, l1;
                    split1(v0, h0, l0); split1(v1, h1, l1);
                    uint32_t hp = ((uint32_t)__bfloat16_as_ushort(h1) << 16) | __bfloat16_as_ushort(h0);
                    uint32_t lp = ((uint32_t)__bfloat16_as_ushort(l1) << 16) | __bfloat16_as_ushort(l0);
                    size_t off = ((size_t)(row >> 8) * (ldc >> 5) + (col >> 5)) * PANEL_B
                               + chunk_off(row & 255, (col & 31) >> 3) + (col & 7) * 2;
                    *(uint32_t*)(outp + off)         = hp;
                    *(uint32_t*)(outp + off + 16384) = lp;
                } else {   // MODE 3: V^T fp16-h transposed panels (B-role h-only)
                    const int mloc = cm0 + wm * 32 + mi * 16 + rl + rh * 8;
                    __half h0 = __float2half_rn(v0);
                    __half h1 = __float2half_rn(v1);
                    size_t pb = ((size_t)(col >> 8) * (SEQ >> 5) + (mloc >> 5)) * PANEL_BH;
                    uint32_t co0 = chunk_off(col & 255, (mloc & 31) >> 3) + (mloc & 7) * 2;
                    uint32_t co1 = chunk_off((col + 1) & 255, (mloc & 31) >> 3) + (mloc & 7) * 2;
                    *(__half*)(outp + pb + co0) = h0;
                    *(__half*)(outp + pb + co1) = h1;
                }
            }
        }
}

// ---------------------------------------------------------------------------
// 1-product fp16 GEMM (context): C = P(fp16 h) * V^T(fp16 h), fp32 acc/out.
// Stage: [Ah 8K][Bh 16K] = 24KB; 4-stage ring; same warp layout.
// ---------------------------------------------------------------------------
#define STAGE1_BYTES 24576
#define SMEM1_BYTES (1024 + NSTAGE * STAGE1_BYTES)   // 99328

__global__ void __launch_bounds__(NTHREADS, 1) context1_tc(float* __restrict__ ctx)
{
    extern __shared__ char smem[];
    const uint32_t sb = smem_u32(smem);
    const int tid = threadIdx.x, lane = tid & 31, wid = tid >> 5;
    const int wm = wid & 3, wn = wid >> 2;
    const int b = blockIdx.z;
    const int m0 = blockIdx.y * 128, n0 = blockIdx.x * 256;

    const char* Ap = g_pph  + (size_t)b * 16 * 64 * PANEL_AH;
    const char* Bp = g_vthp + (size_t)b * 4  * 64 * PANEL_BH;
    float* outf = ctx + (size_t)b * SEQ * HDIM;

    float acc[2][8][4];
#pragma unroll
    for (int i = 0; i < 2; i++)
#pragma unroll
        for (int j = 0; j < 8; j++)
#pragma unroll
            for (int e = 0; e < 4; e++) acc[i][j][e] = 0.f;

    const size_t a_base = (size_t)(m0 >> 7) * 64;
    const size_t b_base = (size_t)(n0 >> 8) * 64;

    if (tid == 0) {
#pragma unroll
        for (int s = 0; s < NSTAGE; s++) MBAR_INIT(sb + s * 8, 1);
    }
    __syncthreads();
    FENCE_ASYNC_SHARED();

    auto issue = [&](int s) {
        const uint32_t mb  = sb + (uint32_t)(s & 3) * 8;
        const uint32_t dst = sb + 1024 + (uint32_t)(s & 3) * STAGE1_BYTES;
        MBAR_EXPECT_TX(mb, (uint32_t)STAGE1_BYTES);
        bulk_g2s(dst,            Ap + (a_base + s) * PANEL_AH, PANEL_AH, mb);
        bulk_g2s(dst + PANEL_AH, Bp + (b_base + s) * PANEL_BH, PANEL_BH, mb);
    };

    if (tid == 0) { issue(0); issue(1); issue(2); }

    const uint32_t lsel = (lane & 7) * 16 + (lane >> 4) * 128 + ((lane >> 3) & 1) * 512;

#pragma unroll 1
    for (int c = 0; c < 64; c++) {
        MBAR_WAIT_PARITY(sb + (c & 3) * 8, (c >> 2) & 1);
        __syncthreads();
        if (tid == 0 && c + 3 < 64) issue(c + 3);

        const uint32_t base = sb + 1024 + (uint32_t)(c & 3) * STAGE1_BYTES;

#pragma unroll
        for (int ks = 0; ks < 2; ks++) {
            const uint32_t koff = (uint32_t)ks * 256;
            uint32_t ah[2][4];
#pragma unroll
            for (int mi = 0; mi < 2; mi++) {
                uint32_t g = (uint32_t)(wm * 4 + mi * 2);
                ldsm4(ah[mi], base + lsel + koff + g * 512);
            }
#pragma unroll
            for (int bi = 0; bi < 4; bi++) {
                uint32_t g = (uint32_t)(wn * 8 + bi * 2);
                uint32_t bh[4];
                ldsm4(bh, base + 8192 + lsel + koff + g * 512);
#pragma unroll
                for (int mi = 0; mi < 2; mi++)
#pragma unroll
                    for (int j = 0; j < 2; j++)
                        mma16816h(acc[mi][bi * 2 + j], ah[mi], bh[j], bh[j + 2]);
            }
        }
    }

    const int rl = lane >> 2, cl = (lane & 3) * 2;
#pragma unroll
    for (int mi = 0; mi < 2; mi++)
#pragma unroll
        for (int ni = 0; ni < 8; ni++) {
            const int col = n0 + wn * 64 + ni * 8 + cl;
#pragma unroll
            for (int rh = 0; rh < 2; rh++) {
                const int row = m0 + wm * 32 + mi * 16 + rl + rh * 8;
                float2 o = {acc[mi][ni][rh * 2 + 0], acc[mi][ni][rh * 2 + 1]};
                *(float2*)(outf + (size_t)row * HDIM + col) = o;
            }
        }
}

// ---------------------------------------------------------------------------
// Fused split: one launch packs x (A-role) + Wq/Wk/Wv (B-role)
// ---------------------------------------------------------------------------
__global__ void __launch_bounds__(256) split_fused(
    const float* __restrict__ x, const float* __restrict__ Wq,
    const float* __restrict__ Wk, const float* __restrict__ Wv,
    char* __restrict__ xp, char* __restrict__ wqp,
    char* __restrict__ wkp, char* __restrict__ wvp)
{
    const int bid = blockIdx.x;
    const float* src;
    char* dst;
    int i;
    bool arole;
    if (bid < 8192) {
        src = x; dst = xp; i = bid * 256 + threadIdx.x; arole = true;
    } else {
        const int w = (bid - 8192) >> 10;
        const int b2 = (bid - 8192) & 1023;
        src = (w == 0) ? Wq : (w == 1) ? Wk : Wv;
        dst = (w == 0) ? wqp : (w == 1) ? wkp : wvp;
        i = b2 * 256 + threadIdx.x; arole = false;
    }
    const int idx = i * 4;
    const int row = idx >> 10, k = idx & 1023;
    float4 v = *(const float4*)(src + idx);
    float f[4] = {v.x, v.y, v.z, v.w};
    uint32_t hp[2], lp[2];
#pragma unroll
    for (int j = 0; j < 2; j++) {
        bf16 h0, l0, h1, l1;
        split1(f[2 * j], h0, l0); split1(f[2 * j + 1], h1, l1);
        hp[j] = ((uint32_t)__bfloat16_as_ushort(h1) << 16) | __bfloat16_as_ushort(h0);
        lp[j] = ((uint32_t)__bfloat16_as_ushort(l1) << 16) | __bfloat16_as_ushort(l0);
    }
    if (arole) {
        size_t off = ((size_t)(row >> 7) * 32 + (k >> 5)) * PANEL_A
                   + chunk_off(row & 127, (k & 31) >> 3) + (k & 7) * 2;
        *(uint2*)(dst + off)        = make_uint2(hp[0], hp[1]);
        *(uint2*)(dst + off + 8192) = make_uint2(lp[0], lp[1]);
    } else {
        size_t off = ((size_t)(row >> 8) * 32 + (k >> 5)) * PANEL_B
                   + chunk_off(row & 255, (k & 31) >> 3) + (k & 7) * 2;
        *(uint2*)(dst + off)         = make_uint2(hp[0], hp[1]);
        *(uint2*)(dst + off + 16384) = make_uint2(lp[0], lp[1]);
    }
}

// ---------------------------------------------------------------------------
// GEMM kernels
// ---------------------------------------------------------------------------
__global__ void __launch_bounds__(NTHREADS, 1) qkv_qk_tc(
    const float* __restrict__ bq, const float* __restrict__ bk)
{
    const int m0 = blockIdx.y * 128;
    const int n0 = blockIdx.x * 256;
    if (blockIdx.z == 0) {
        gemm_core<0, 32, 0>(g_xp, g_wqp, HDIM, bq, g_qp, nullptr, HDIM, m0, n0, 0);
    } else {
        gemm_core<1, 32, 0>(g_xp, g_wkp, HDIM, bk, g_kp, nullptr, HDIM, m0, n0, 0);
    }
}

__global__ void __launch_bounds__(NTHREADS, 1) vt_tc(const float* __restrict__ bv)
{
    const int m0 = blockIdx.y * 128;
    const int n0 = blockIdx.x * 256;
    const int b = m0 >> 11;
    gemm_core<3, 32, 0>(g_xp, g_wvp, HDIM, bv,
                        g_vthp + (size_t)b * 4 * 64 * PANEL_BH, nullptr, SEQ,
                        m0, n0, m0 & (SEQ - 1));
}

__global__ void __launch_bounds__(NTHREADS, 1) scores_tc()
{
    const int z = blockIdx.z;
    const int b = z & (BATCH - 1), half = z >> 2;
    const char* qp = g_qp + (size_t)b * 16 * 32 * PANEL_A;
    const char* kp = g_kp + (size_t)b * 8 * 32 * PANEL_B;
    const int m0 = blockIdx.y * 128, n0 = blockIdx.x * 256;
    if (half == 0) {
        gemm_core<2, 32, 0>(qp, kp, HDIM / 2, nullptr, nullptr,
                            g_p + (size_t)b * SEQ * SEQ, SEQ, m0, n0, 0);
    } else {
        gemm_core<2, 32, 16>(qp, kp, HDIM / 2, nullptr, nullptr,
                             g_p2 + (size_t)b * SEQ * SEQ, SEQ, m0, n0, 0);
    }
}

// ---------------------------------------------------------------------------
// Softmax: sum split-K partials, softmax, store probs as fp16-h panels
// ---------------------------------------------------------------------------
__global__ void __launch_bounds__(256) softmax_kernel()
{
    const int row = blockIdx.x;
    const float4* p4 = (const float4*)(g_p  + (size_t)row * SEQ) + threadIdx.x * 2;
    const float4* q4 = (const float4*)(g_p2 + (size_t)row * SEQ) + threadIdx.x * 2;
    const int tid = threadIdx.x;

    float4 va = p4[0], vb = p4[1];
    float4 wa = q4[0], wb = q4[1];
    float v[8] = {va.x + wa.x, va.y + wa.y, va.z + wa.z, va.w + wa.w,
                  vb.x + wb.x, vb.y + wb.y, vb.z + wb.z, vb.w + wb.w};
    float m = v[0];
#pragma unroll
    for (int i = 1; i < 8; i++) m = fmaxf(m, v[i]);

    __shared__ float red[8];
#pragma unroll
    for (int o = 16; o; o >>= 1) m = fmaxf(m, __shfl_xor_sync(0xffffffffu, m, o));
    if ((tid & 31) == 0) red[tid >> 5] = m;
    __syncthreads();
    m = red[0];
#pragma unroll
    for (int i = 1; i < 8; i++) m = fmaxf(m, red[i]);
    __syncthreads();

    float s = 0.f;
#pragma unroll
    for (int i = 0; i < 8; i++) {
        v[i] = __expf(v[i] - m);
        s += v[i];
    }
#pragma unroll
    for (int o = 16; o; o >>= 1) s += __shfl_xor_sync(0xffffffffu, s, o);
    if ((tid & 31) == 0) red[tid >> 5] = s;
    __syncthreads();
    float tot = 0.f;
#pragma unroll
    for (int i = 0; i < 8; i++) tot += red[i];
    const float inv = 1.0f / tot;

    uint32_t hp[4];
#pragma unroll
    for (int j = 0; j < 4; j++) {
        __half h0 = __float2half_rn(v[2 * j] * inv);
        __half h1 = __float2half_rn(v[2 * j + 1] * inv);
        hp[j] = ((uint32_t)__half_as_ushort(h1) << 16) | __half_as_ushort(h0);
    }
    const int col0 = tid * 8;
    const size_t off = ((size_t)(row >> 7) * 64 + (col0 >> 5)) * PANEL_AH
                     + chunk_off(row & 127, (col0 & 31) >> 3);
    *(uint4*)(g_pph + off) = make_uint4(hp[0], hp[1], hp[2], hp[3]);
}

// ---------------------------------------------------------------------------
// Column sums of probs (fp16-h panels), per-panel reduction
// ---------------------------------------------------------------------------
__global__ void __launch_bounds__(256) colsum_kernel(float* __restrict__ out)
{
    const int pk = blockIdx.x;   // 0..63 k-panel
    const int pr = blockIdx.y;   // 0..63 row-panel
    const char* panel = g_pph + ((size_t)pr * 64 + pk) * PANEL_AH;
    const int tid = threadIdx.x;
    const int col = tid & 31;
    const int rg  = tid >> 5;

    const uint32_t cbase = ((col & 31) >> 3) * 128 + (col & 7) * 2;
    float s = 0.f;
#pragma unroll
    for (int r = rg * 16; r < rg * 16 + 16; r++) {
        uint32_t off = (uint32_t)((r & 7) * 16 + 4 * (r >> 3) * 128) + cbase;
        s += __half2float(*(const __half*)(panel + off));
    }
    __shared__ float part[256];
    part[tid] = s;
    __syncthreads();
    if (tid < 32) {
        float t = 0.f;
#pragma unroll
        for (int j = 0; j < 8; j++) t += part[tid + 32 * j];
        const int batch = pr >> 4;
        atomicAdd(out + batch * SEQ + pk * 32 + tid, t);
    }
}

// ---------------------------------------------------------------------------
extern "C" void kernel_launch(void* const* d_in, const int* in_sizes, int n_in,
                              void* d_out, int out_size)
{
    const float* x  = (const float*)d_in[0];
    const float* Wq = (const float*)d_in[1];
    const float* bq = (const float*)d_in[2];
    const float* Wk = (const float*)d_in[3];
    const float* bk = (const float*)d_in[4];
    const float* Wv = (const float*)d_in[5];
    const float* bv = (const float*)d_in[6];

    float* ctx = (float*)d_out;
    float* sc  = ctx + (size_t)BATCH * SEQ * HDIM;

    cudaFuncSetAttribute((const void*)qkv_qk_tc,
                         cudaFuncAttributeMaxDynamicSharedMemorySize, SMEM_BYTES);
    cudaFuncSetAttribute((const void*)vt_tc,
                         cudaFuncAttributeMaxDynamicSharedMemorySize, SMEM_BYTES);
    cudaFuncSetAttribute((const void*)scores_tc,
                         cudaFuncAttributeMaxDynamicSharedMemorySize, SMEM_BYTES);
    cudaFuncSetAttribute((const void*)context1_tc,
                         cudaFuncAttributeMaxDynamicSharedMemorySize, SMEM1_BYTES);

    char *xp, *wqp, *wkp, *wvp;
    cudaGetSymbolAddress((void**)&xp,  g_xp);
    cudaGetSymbolAddress((void**)&wqp, g_wqp);
    cudaGetSymbolAddress((void**)&wkp, g_wkp);
    cudaGetSymbolAddress((void**)&wvp, g_wvp);

    static cudaStream_t s2 = nullptr;
    static cudaEvent_t evFork = nullptr, evJoin = nullptr;
    static cudaEvent_t evSm = nullptr, evJoin2 = nullptr;
    if (s2 == nullptr) {
        cudaStreamCreateWithFlags(&s2, cudaStreamNonBlocking);
        cudaEventCreateWithFlags(&evFork, cudaEventDisableTiming);
        cudaEventCreateWithFlags(&evJoin, cudaEventDisableTiming);
        cudaEventCreateWithFlags(&evSm, cudaEventDisableTiming);
        cudaEventCreateWithFlags(&evJoin2, cudaEventDisableTiming);
    }

    cudaMemsetAsync(sc, 0, (size_t)BATCH * SEQ * sizeof(float));

    split_fused<<<8192 + 3 * 1024, 256>>>(x, Wq, Wk, Wv, xp, wqp, wkp, wvp);
    cudaEventRecord(evFork, 0);

    // Submit qk FIRST so its CTAs win the dispatcher; vt then fills qk's tail
    // wave and overlaps scores/softmax on the main stream.
    qkv_qk_tc<<<dim3(HDIM / 256, MTOT / 128, 2), NTHREADS, SMEM_BYTES>>>(bq, bk);

    cudaStreamWaitEvent(s2, evFork, 0);
    vt_tc<<<dim3(HDIM / 256, MTOT / 128), NTHREADS, SMEM_BYTES, s2>>>(bv);
    cudaEventRecord(evJoin, s2);

    scores_tc<<<dim3(SEQ / 256, SEQ / 128, BATCH * 2), NTHREADS, SMEM_BYTES>>>();
    softmax_kernel<<<MTOT, 256>>>();
    cudaEventRecord(evSm, 0);

    // colsum on s2 (needs only softmax); context1 runs concurrently on main.
    cudaStreamWaitEvent(s2, evSm, 0);
    colsum_kernel<<<dim3(64, 64), 256, 0, s2>>>(sc);
    cudaEventRecord(evJoin2, s2);

    cudaStreamWaitEvent(0, evJoin, 0);
    context1_tc<<<dim3(HDIM / 256, SEQ / 128, BATCH), NTHREADS, SMEM1_BYTES>>>(ctx);
    cudaStreamWaitEvent(0, evJoin2, 0);
}